// round 1
// baseline (speedup 1.0000x reference)
#include <cuda_runtime.h>
#include <cuda_bf16.h>
#include <math.h>
#include <float.h>

// Problem constants
#define B_   2
#define S_   2048
#define HID_ 768
#define H_   12
#define D_   64
#define BS_  256
#define NB_  8
#define TK_  3
#define M_   (B_ * S_)          // 4096 token rows

// Scratch (device globals; no runtime allocation allowed)
__device__ float g_q[B_ * H_ * S_ * D_];
__device__ float g_k[B_ * H_ * S_ * D_];
__device__ float g_v[B_ * H_ * S_ * D_];
__device__ float g_attn[B_ * S_ * HID_];
__device__ float g_brep[B_ * H_ * NB_ * D_];
__device__ unsigned char g_mask[B_ * H_ * S_];

// ---------------------------------------------------------------------------
// GEMM: C[M,N] = A[M,K] * W[N,K]^T   (fp32, 128x128 tile, BK=8, 8x8 microtile)
// mode 0/1/2: A = hidden, write into g_q/g_k/g_v with (b,h,s,d) layout
// mode 3:     A = g_attn, write plain row-major into out
// ---------------------------------------------------------------------------
__global__ __launch_bounds__(256) void gemm_kernel(const float* A,
                                                   const float* __restrict__ W,
                                                   float* out, int mode) {
    const int K = HID_;
    __shared__ float As[8][128];
    __shared__ float Bs[8][128];

    const float* Ap = (mode == 3) ? g_attn : A;

    const int bm = blockIdx.y * 128;
    const int bn = blockIdx.x * 128;
    const int tid = threadIdx.x;
    const int ty = tid >> 4;       // 0..15
    const int tx = tid & 15;       // 0..15

    const int lr = tid >> 1;       // 0..127 (tile row for loads)
    const int lk = (tid & 1) * 4;  // 0 or 4

    float acc[8][8];
#pragma unroll
    for (int i = 0; i < 8; ++i)
#pragma unroll
        for (int j = 0; j < 8; ++j) acc[i][j] = 0.0f;

    const float* aptr = Ap + (size_t)(bm + lr) * K + lk;
    const float* bptr = W + (size_t)(bn + lr) * K + lk;

    for (int k0 = 0; k0 < K; k0 += 8) {
        float4 av = *(const float4*)(aptr + k0);
        float4 bv = *(const float4*)(bptr + k0);
        As[lk + 0][lr] = av.x; As[lk + 1][lr] = av.y;
        As[lk + 2][lr] = av.z; As[lk + 3][lr] = av.w;
        Bs[lk + 0][lr] = bv.x; Bs[lk + 1][lr] = bv.y;
        Bs[lk + 2][lr] = bv.z; Bs[lk + 3][lr] = bv.w;
        __syncthreads();
#pragma unroll
        for (int k = 0; k < 8; ++k) {
            float a[8], b[8];
            float4 a0 = *(const float4*)&As[k][ty * 8];
            float4 a1 = *(const float4*)&As[k][ty * 8 + 4];
            float4 b0 = *(const float4*)&Bs[k][tx * 8];
            float4 b1 = *(const float4*)&Bs[k][tx * 8 + 4];
            a[0]=a0.x; a[1]=a0.y; a[2]=a0.z; a[3]=a0.w;
            a[4]=a1.x; a[5]=a1.y; a[6]=a1.z; a[7]=a1.w;
            b[0]=b0.x; b[1]=b0.y; b[2]=b0.z; b[3]=b0.w;
            b[4]=b1.x; b[5]=b1.y; b[6]=b1.z; b[7]=b1.w;
#pragma unroll
            for (int i = 0; i < 8; ++i)
#pragma unroll
                for (int j = 0; j < 8; ++j) acc[i][j] = fmaf(a[i], b[j], acc[i][j]);
        }
        __syncthreads();
    }

    // Epilogue
    float* dst = (mode == 0) ? g_q : (mode == 1) ? g_k : (mode == 2) ? g_v : out;
#pragma unroll
    for (int i = 0; i < 8; ++i) {
        int row = bm + ty * 8 + i;
#pragma unroll
        for (int jj = 0; jj < 2; ++jj) {
            int col = bn + tx * 8 + jj * 4;
            float4 v = make_float4(acc[i][jj * 4 + 0], acc[i][jj * 4 + 1],
                                   acc[i][jj * 4 + 2], acc[i][jj * 4 + 3]);
            if (mode < 3) {
                int bb = row >> 11;          // / S_
                int ss = row & (S_ - 1);
                int hh = col >> 6;           // / D_
                int dd = col & 63;
                *(float4*)(dst + (((size_t)(bb * H_ + hh) * S_ + ss) << 6) + dd) = v;
            } else {
                *(float4*)(dst + (size_t)row * HID_ + col) = v;
            }
        }
    }
}

// ---------------------------------------------------------------------------
// RoPE in-place on g_q and g_k.  One thread per (tensor, row, pair i<32).
// ---------------------------------------------------------------------------
__global__ __launch_bounds__(256) void rope_kernel() {
    const int PER = B_ * H_ * S_ * 32;   // 1,572,864
    int idx = blockIdx.x * 256 + threadIdx.x;
    if (idx >= 2 * PER) return;
    float* base = (idx < PER) ? g_q : g_k;
    int r = (idx < PER) ? idx : idx - PER;
    int i = r & 31;
    int rowid = r >> 5;
    int s = rowid & (S_ - 1);
    // inv_freq[i] = 10000^(-2i/64), computed in double for fidelity to fp32 ref
    float inv = (float)exp(-9.210340371976184 * (double)i / 32.0);
    float ang = (float)s * inv;
    float c = cosf(ang);
    float sn = sinf(ang);
    float* p = base + (size_t)rowid * 64;
    float x1 = p[i];
    float x2 = p[i + 32];
    p[i]      = x1 * c - x2 * sn;
    p[i + 32] = x2 * c + x1 * sn;
}

// ---------------------------------------------------------------------------
// Block representatives: mean of (roped) K over each 256-token block.
// grid = B*H*NB blocks, 64 threads (one per dim)
// ---------------------------------------------------------------------------
__global__ __launch_bounds__(64) void brep_kernel() {
    int blk = blockIdx.x;          // bh*8 + nb
    int bh = blk >> 3;
    int nbk = blk & 7;
    int d = threadIdx.x;
    const float* kp = g_k + ((size_t)bh * S_ + nbk * BS_) * 64 + d;
    float sum = 0.0f;
    for (int i = 0; i < BS_; ++i) sum += kp[(size_t)i * 64];
    g_brep[(size_t)blk * 64 + d] = sum * (1.0f / 256.0f);
}

// ---------------------------------------------------------------------------
// Top-3 block selection per query.  Replicates jax.lax.top_k tie-breaking
// (descending value, lower index first on ties, including -inf ties).
// grid = B*H*S/128, 128 threads (one query per thread)
// ---------------------------------------------------------------------------
__global__ __launch_bounds__(128) void select_kernel() {
    __shared__ float Qsh[128 * 65];
    __shared__ float Bsh[NB_ * 64];
    const int tid = threadIdx.x;
    const size_t qbase = (size_t)blockIdx.x * 128;   // linear (b,h,s) index
    const int bh = (int)(qbase >> 11);

    for (int off = tid; off < NB_ * 64; off += 128)
        Bsh[off] = g_brep[(size_t)bh * (NB_ * 64) + off];
    const float* qp = g_q + qbase * 64;
    for (int off = tid; off < 128 * 64; off += 128)
        Qsh[(off >> 6) * 65 + (off & 63)] = qp[off];
    __syncthreads();

    int qidx = (int)qbase + tid;
    int s = qidx & (S_ - 1);
    int cur = s >> 8;
    const float* qr = Qsh + tid * 65;

    float sc[NB_];
#pragma unroll
    for (int j = 0; j < NB_; ++j) {
        if (j > cur) { sc[j] = -INFINITY; continue; }
        if (j == cur) { sc[j] = 3.402823466e38f; continue; }
        float dd = 0.0f;
#pragma unroll 8
        for (int d = 0; d < 64; ++d) dd = fmaf(qr[d], Bsh[j * 64 + d], dd);
        sc[j] = dd;
    }

    unsigned msk = 0;
    bool used[NB_];
#pragma unroll
    for (int j = 0; j < NB_; ++j) used[j] = false;
#pragma unroll
    for (int t = 0; t < TK_; ++t) {
        int bi = -1; float bv = 0.0f;
#pragma unroll
        for (int j = 0; j < NB_; ++j) {
            if (!used[j] && (bi < 0 || sc[j] > bv)) { bi = j; bv = sc[j]; }
        }
        used[bi] = true;
        msk |= 1u << bi;
    }
    g_mask[qidx] = (unsigned char)msk;
}

// ---------------------------------------------------------------------------
// Sparse flash attention.  grid = (S/64, H, B), 256 threads.
// 64 queries x 64-key tiles; per-query block bitmask; online softmax.
// Shared: Qs[d][m] 16KB, KP (K tile [d][key], then P [row][key]) 16KB,
//         Vs[key][d] 16KB  => exactly 48KB dynamic.
// ---------------------------------------------------------------------------
__global__ __launch_bounds__(256) void attn_kernel() {
    extern __shared__ float sm[];
    float* Qs = sm;            // [64][64] layout [d][m]
    float* KP = sm + 4096;     // K tile [d][key], later P [row][key]
    float* Vs = sm + 8192;     // [key][d]

    const int qt = blockIdx.x, h = blockIdx.y, b = blockIdx.z;
    const int q0 = qt * 64;
    const int tid = threadIdx.x;
    const int ty = tid >> 4, tx = tid & 15;
    const int bh = b * H_ + h;

    // Load Q tile transposed into [d][m]
    {
        int m = tid >> 2;
        int dseg = (tid & 3) << 4;
        const float* p = g_q + ((size_t)bh * S_ + q0 + m) * 64 + dseg;
#pragma unroll
        for (int i = 0; i < 4; ++i) {
            float4 v = *(const float4*)(p + i * 4);
            int d = dseg + i * 4;
            Qs[(d + 0) * 64 + m] = v.x;
            Qs[(d + 1) * 64 + m] = v.y;
            Qs[(d + 2) * 64 + m] = v.z;
            Qs[(d + 3) * 64 + m] = v.w;
        }
    }

    const int cur = q0 >> 8;
    const int nkt = ((cur >= 2) ? (cur + 1) : 3) * 4;   // key tiles of 64

    unsigned msk[4];
#pragma unroll
    for (int ri = 0; ri < 4; ++ri)
        msk[ri] = g_mask[(size_t)bh * S_ + q0 + ty * 4 + ri];

    float mrow[4], lrow[4], acc[4][4];
#pragma unroll
    for (int ri = 0; ri < 4; ++ri) {
        mrow[ri] = -INFINITY;
        lrow[ri] = 0.0f;
#pragma unroll
        for (int ci = 0; ci < 4; ++ci) acc[ri][ci] = 0.0f;
    }

    const float* kbase = g_k + (size_t)bh * S_ * 64;
    const float* vbase = g_v + (size_t)bh * S_ * 64;

    for (int kt = 0; kt < nkt; ++kt) {
        const int k0 = kt * 64;
        const int jb = kt >> 2;           // key block (0..7)
        __syncthreads();                  // prior PV done before overwriting tiles
        {
            int key = tid >> 2;
            int dseg = (tid & 3) << 4;
            const float* kp = kbase + (size_t)(k0 + key) * 64 + dseg;
            const float* vp = vbase + (size_t)(k0 + key) * 64 + dseg;
#pragma unroll
            for (int i = 0; i < 4; ++i) {
                float4 kv = *(const float4*)(kp + i * 4);
                int d = dseg + i * 4;
                KP[(d + 0) * 64 + key] = kv.x;
                KP[(d + 1) * 64 + key] = kv.y;
                KP[(d + 2) * 64 + key] = kv.z;
                KP[(d + 3) * 64 + key] = kv.w;
                *(float4*)(Vs + key * 64 + d) = *(const float4*)(vp + i * 4);
            }
        }
        __syncthreads();

        // Scores: S = Q K^T over d
        float s[4][4];
#pragma unroll
        for (int ri = 0; ri < 4; ++ri)
#pragma unroll
            for (int ci = 0; ci < 4; ++ci) s[ri][ci] = 0.0f;
#pragma unroll 4
        for (int d = 0; d < 64; ++d) {
            float4 aq = *(const float4*)(Qs + d * 64 + (ty << 2));
            float4 bk = *(const float4*)(KP + d * 64 + (tx << 2));
            float a[4] = {aq.x, aq.y, aq.z, aq.w};
            float bb[4] = {bk.x, bk.y, bk.z, bk.w};
#pragma unroll
            for (int ri = 0; ri < 4; ++ri)
#pragma unroll
                for (int ci = 0; ci < 4; ++ci)
                    s[ri][ci] = fmaf(a[ri], bb[ci], s[ri][ci]);
        }
        __syncthreads();   // everyone done reading KP before writing P into it

        // Mask + online softmax, write P into KP
#pragma unroll
        for (int ri = 0; ri < 4; ++ri) {
            const int qrow = q0 + ty * 4 + ri;
            const bool sel = (msk[ri] >> jb) & 1u;
            float mx = -INFINITY;
#pragma unroll
            for (int ci = 0; ci < 4; ++ci) {
                int kg = k0 + tx * 4 + ci;
                bool valid = sel && (jb != cur || kg <= qrow);
                float sv = valid ? s[ri][ci] * 0.125f : -INFINITY;
                s[ri][ci] = sv;
                mx = fmaxf(mx, sv);
            }
#pragma unroll
            for (int off = 8; off >= 1; off >>= 1)
                mx = fmaxf(mx, __shfl_xor_sync(0xffffffffu, mx, off, 16));
            float newm = fmaxf(mrow[ri], mx);
            float fac;
            if (mrow[ri] == -INFINITY)
                fac = (newm == -INFINITY) ? 1.0f : 0.0f;
            else
                fac = __expf(mrow[ri] - newm);
            float rs = 0.0f;
#pragma unroll
            for (int ci = 0; ci < 4; ++ci) {
                float pv = (s[ri][ci] == -INFINITY) ? 0.0f : __expf(s[ri][ci] - newm);
                KP[(ty * 4 + ri) * 64 + tx * 4 + ci] = pv;
                rs += pv;
            }
#pragma unroll
            for (int off = 8; off >= 1; off >>= 1)
                rs += __shfl_xor_sync(0xffffffffu, rs, off, 16);
            lrow[ri] = lrow[ri] * fac + rs;
            mrow[ri] = newm;
#pragma unroll
            for (int ci = 0; ci < 4; ++ci) acc[ri][ci] *= fac;
        }
        __syncthreads();

        // acc += P @ V
#pragma unroll 4
        for (int kk = 0; kk < 64; ++kk) {
            float4 vv = *(const float4*)(Vs + kk * 64 + (tx << 2));
            float p0 = KP[(ty * 4 + 0) * 64 + kk];
            float p1 = KP[(ty * 4 + 1) * 64 + kk];
            float p2 = KP[(ty * 4 + 2) * 64 + kk];
            float p3 = KP[(ty * 4 + 3) * 64 + kk];
            acc[0][0] = fmaf(p0, vv.x, acc[0][0]);
            acc[0][1] = fmaf(p0, vv.y, acc[0][1]);
            acc[0][2] = fmaf(p0, vv.z, acc[0][2]);
            acc[0][3] = fmaf(p0, vv.w, acc[0][3]);
            acc[1][0] = fmaf(p1, vv.x, acc[1][0]);
            acc[1][1] = fmaf(p1, vv.y, acc[1][1]);
            acc[1][2] = fmaf(p1, vv.z, acc[1][2]);
            acc[1][3] = fmaf(p1, vv.w, acc[1][3]);
            acc[2][0] = fmaf(p2, vv.x, acc[2][0]);
            acc[2][1] = fmaf(p2, vv.y, acc[2][1]);
            acc[2][2] = fmaf(p2, vv.z, acc[2][2]);
            acc[2][3] = fmaf(p2, vv.w, acc[2][3]);
            acc[3][0] = fmaf(p3, vv.x, acc[3][0]);
            acc[3][1] = fmaf(p3, vv.y, acc[3][1]);
            acc[3][2] = fmaf(p3, vv.z, acc[3][2]);
            acc[3][3] = fmaf(p3, vv.w, acc[3][3]);
        }
    }

    // Epilogue: normalize and write to (b, s, h, d) layout
#pragma unroll
    for (int ri = 0; ri < 4; ++ri) {
        int qrow = q0 + ty * 4 + ri;
        float inv = 1.0f / lrow[ri];
        float4 o = make_float4(acc[ri][0] * inv, acc[ri][1] * inv,
                               acc[ri][2] * inv, acc[ri][3] * inv);
        *(float4*)(g_attn + ((size_t)(b * S_ + qrow) * H_ + h) * 64 + (tx << 2)) = o;
    }
}

// ---------------------------------------------------------------------------
extern "C" void kernel_launch(void* const* d_in, const int* in_sizes, int n_in,
                              void* d_out, int out_size) {
    const float* hidden = (const float*)d_in[0];
    const float* Wq = (const float*)d_in[1];
    const float* Wk = (const float*)d_in[2];
    const float* Wv = (const float*)d_in[3];
    const float* Wo = (const float*)d_in[4];

    dim3 ggrid(HID_ / 128, M_ / 128);   // (6, 32)

    gemm_kernel<<<ggrid, 256>>>(hidden, Wq, nullptr, 0);
    gemm_kernel<<<ggrid, 256>>>(hidden, Wk, nullptr, 1);
    gemm_kernel<<<ggrid, 256>>>(hidden, Wv, nullptr, 2);

    rope_kernel<<<(2 * B_ * H_ * S_ * 32 + 255) / 256, 256>>>();
    brep_kernel<<<B_ * H_ * NB_, 64>>>();
    select_kernel<<<B_ * H_ * S_ / 128, 128>>>();

    attn_kernel<<<dim3(S_ / 64, H_, B_), 256, 48 * 1024>>>();

    gemm_kernel<<<ggrid, 256>>>(nullptr, Wo, (float*)d_out, 3);
}

// round 2
// speedup vs baseline: 1.0001x; 1.0001x over previous
#include <cuda_runtime.h>
#include <cuda_bf16.h>
#include <math.h>
#include <float.h>

// Problem constants
#define B_   2
#define S_   2048
#define HID_ 768
#define H_   12
#define D_   64
#define BS_  256
#define NB_  8
#define TK_  3
#define M_   (B_ * S_)          // 4096 token rows

// Scratch (device globals; no runtime allocation allowed)
__device__ float g_q[B_ * H_ * S_ * D_];
__device__ float g_k[B_ * H_ * S_ * D_];
__device__ float g_v[B_ * H_ * S_ * D_];
__device__ float g_attn[B_ * S_ * HID_];
__device__ float g_brep[B_ * H_ * NB_ * D_];
__device__ unsigned char g_mask[B_ * H_ * S_];

// ---------------------------------------------------------------------------
// GEMM: C[M,N] = A[M,K] * W[N,K]^T   (fp32, 128x128 tile, BK=8, 8x8 microtile)
// mode 0/1/2: A = hidden, write into g_q/g_k/g_v with (b,h,s,d) layout
// mode 3:     A = g_attn, write plain row-major into out
// ---------------------------------------------------------------------------
__global__ __launch_bounds__(256) void gemm_kernel(const float* A,
                                                   const float* __restrict__ W,
                                                   float* out, int mode) {
    const int K = HID_;
    __shared__ float As[8][128];
    __shared__ float Bs[8][128];

    const float* Ap = (mode == 3) ? g_attn : A;

    const int bm = blockIdx.y * 128;
    const int bn = blockIdx.x * 128;
    const int tid = threadIdx.x;
    const int ty = tid >> 4;       // 0..15
    const int tx = tid & 15;       // 0..15

    const int lr = tid >> 1;       // 0..127 (tile row for loads)
    const int lk = (tid & 1) * 4;  // 0 or 4

    float acc[8][8];
#pragma unroll
    for (int i = 0; i < 8; ++i)
#pragma unroll
        for (int j = 0; j < 8; ++j) acc[i][j] = 0.0f;

    const float* aptr = Ap + (size_t)(bm + lr) * K + lk;
    const float* bptr = W + (size_t)(bn + lr) * K + lk;

    for (int k0 = 0; k0 < K; k0 += 8) {
        float4 av = *(const float4*)(aptr + k0);
        float4 bv = *(const float4*)(bptr + k0);
        As[lk + 0][lr] = av.x; As[lk + 1][lr] = av.y;
        As[lk + 2][lr] = av.z; As[lk + 3][lr] = av.w;
        Bs[lk + 0][lr] = bv.x; Bs[lk + 1][lr] = bv.y;
        Bs[lk + 2][lr] = bv.z; Bs[lk + 3][lr] = bv.w;
        __syncthreads();
#pragma unroll
        for (int k = 0; k < 8; ++k) {
            float a[8], b[8];
            float4 a0 = *(const float4*)&As[k][ty * 8];
            float4 a1 = *(const float4*)&As[k][ty * 8 + 4];
            float4 b0 = *(const float4*)&Bs[k][tx * 8];
            float4 b1 = *(const float4*)&Bs[k][tx * 8 + 4];
            a[0]=a0.x; a[1]=a0.y; a[2]=a0.z; a[3]=a0.w;
            a[4]=a1.x; a[5]=a1.y; a[6]=a1.z; a[7]=a1.w;
            b[0]=b0.x; b[1]=b0.y; b[2]=b0.z; b[3]=b0.w;
            b[4]=b1.x; b[5]=b1.y; b[6]=b1.z; b[7]=b1.w;
#pragma unroll
            for (int i = 0; i < 8; ++i)
#pragma unroll
                for (int j = 0; j < 8; ++j) acc[i][j] = fmaf(a[i], b[j], acc[i][j]);
        }
        __syncthreads();
    }

    // Epilogue
    float* dst = (mode == 0) ? g_q : (mode == 1) ? g_k : (mode == 2) ? g_v : out;
#pragma unroll
    for (int i = 0; i < 8; ++i) {
        int row = bm + ty * 8 + i;
#pragma unroll
        for (int jj = 0; jj < 2; ++jj) {
            int col = bn + tx * 8 + jj * 4;
            float4 v = make_float4(acc[i][jj * 4 + 0], acc[i][jj * 4 + 1],
                                   acc[i][jj * 4 + 2], acc[i][jj * 4 + 3]);
            if (mode < 3) {
                int bb = row >> 11;          // / S_
                int ss = row & (S_ - 1);
                int hh = col >> 6;           // / D_
                int dd = col & 63;
                *(float4*)(dst + (((size_t)(bb * H_ + hh) * S_ + ss) << 6) + dd) = v;
            } else {
                *(float4*)(dst + (size_t)row * HID_ + col) = v;
            }
        }
    }
}

// ---------------------------------------------------------------------------
// RoPE in-place on g_q and g_k.  One thread per (tensor, row, pair i<32).
// ---------------------------------------------------------------------------
__global__ __launch_bounds__(256) void rope_kernel() {
    const int PER = B_ * H_ * S_ * 32;   // 1,572,864
    int idx = blockIdx.x * 256 + threadIdx.x;
    if (idx >= 2 * PER) return;
    float* base = (idx < PER) ? g_q : g_k;
    int r = (idx < PER) ? idx : idx - PER;
    int i = r & 31;
    int rowid = r >> 5;
    int s = rowid & (S_ - 1);
    // inv_freq[i] = 10000^(-2i/64), computed in double for fidelity to fp32 ref
    float inv = (float)exp(-9.210340371976184 * (double)i / 32.0);
    float ang = (float)s * inv;
    float c = cosf(ang);
    float sn = sinf(ang);
    float* p = base + (size_t)rowid * 64;
    float x1 = p[i];
    float x2 = p[i + 32];
    p[i]      = x1 * c - x2 * sn;
    p[i + 32] = x2 * c + x1 * sn;
}

// ---------------------------------------------------------------------------
// Block representatives: mean of (roped) K over each 256-token block.
// grid = B*H*NB blocks, 64 threads (one per dim)
// ---------------------------------------------------------------------------
__global__ __launch_bounds__(64) void brep_kernel() {
    int blk = blockIdx.x;          // bh*8 + nb
    int bh = blk >> 3;
    int nbk = blk & 7;
    int d = threadIdx.x;
    const float* kp = g_k + ((size_t)bh * S_ + nbk * BS_) * 64 + d;
    float sum = 0.0f;
    for (int i = 0; i < BS_; ++i) sum += kp[(size_t)i * 64];
    g_brep[(size_t)blk * 64 + d] = sum * (1.0f / 256.0f);
}

// ---------------------------------------------------------------------------
// Top-3 block selection per query.  Replicates jax.lax.top_k tie-breaking
// (descending value, lower index first on ties, including -inf ties).
// grid = B*H*S/128, 128 threads (one query per thread)
// ---------------------------------------------------------------------------
__global__ __launch_bounds__(128) void select_kernel() {
    __shared__ float Qsh[128 * 65];
    __shared__ float Bsh[NB_ * 64];
    const int tid = threadIdx.x;
    const size_t qbase = (size_t)blockIdx.x * 128;   // linear (b,h,s) index
    const int bh = (int)(qbase >> 11);

    for (int off = tid; off < NB_ * 64; off += 128)
        Bsh[off] = g_brep[(size_t)bh * (NB_ * 64) + off];
    const float* qp = g_q + qbase * 64;
    for (int off = tid; off < 128 * 64; off += 128)
        Qsh[(off >> 6) * 65 + (off & 63)] = qp[off];
    __syncthreads();

    int qidx = (int)qbase + tid;
    int s = qidx & (S_ - 1);
    int cur = s >> 8;
    const float* qr = Qsh + tid * 65;

    float sc[NB_];
#pragma unroll
    for (int j = 0; j < NB_; ++j) {
        if (j > cur) { sc[j] = -INFINITY; continue; }
        if (j == cur) { sc[j] = 3.402823466e38f; continue; }
        float dd = 0.0f;
#pragma unroll 8
        for (int d = 0; d < 64; ++d) dd = fmaf(qr[d], Bsh[j * 64 + d], dd);
        sc[j] = dd;
    }

    unsigned msk = 0;
    bool used[NB_];
#pragma unroll
    for (int j = 0; j < NB_; ++j) used[j] = false;
#pragma unroll
    for (int t = 0; t < TK_; ++t) {
        int bi = -1; float bv = 0.0f;
#pragma unroll
        for (int j = 0; j < NB_; ++j) {
            if (!used[j] && (bi < 0 || sc[j] > bv)) { bi = j; bv = sc[j]; }
        }
        used[bi] = true;
        msk |= 1u << bi;
    }
    g_mask[qidx] = (unsigned char)msk;
}

// ---------------------------------------------------------------------------
// Sparse flash attention.  grid = (S/64, H, B), 256 threads.
// 64 queries x 64-key tiles; per-query block bitmask; online softmax.
// Shared: Qs[d][m] 16KB, KP (K tile [d][key], then P [row][key]) 16KB,
//         Vs[key][d] 16KB  => exactly 48KB dynamic.
// ---------------------------------------------------------------------------
__global__ __launch_bounds__(256) void attn_kernel() {
    extern __shared__ float sm[];
    float* Qs = sm;            // [64][64] layout [d][m]
    float* KP = sm + 4096;     // K tile [d][key], later P [row][key]
    float* Vs = sm + 8192;     // [key][d]

    const int qt = blockIdx.x, h = blockIdx.y, b = blockIdx.z;
    const int q0 = qt * 64;
    const int tid = threadIdx.x;
    const int ty = tid >> 4, tx = tid & 15;
    const int bh = b * H_ + h;

    // Load Q tile transposed into [d][m]
    {
        int m = tid >> 2;
        int dseg = (tid & 3) << 4;
        const float* p = g_q + ((size_t)bh * S_ + q0 + m) * 64 + dseg;
#pragma unroll
        for (int i = 0; i < 4; ++i) {
            float4 v = *(const float4*)(p + i * 4);
            int d = dseg + i * 4;
            Qs[(d + 0) * 64 + m] = v.x;
            Qs[(d + 1) * 64 + m] = v.y;
            Qs[(d + 2) * 64 + m] = v.z;
            Qs[(d + 3) * 64 + m] = v.w;
        }
    }

    const int cur = q0 >> 8;
    const int nkt = ((cur >= 2) ? (cur + 1) : 3) * 4;   // key tiles of 64

    unsigned msk[4];
#pragma unroll
    for (int ri = 0; ri < 4; ++ri)
        msk[ri] = g_mask[(size_t)bh * S_ + q0 + ty * 4 + ri];

    float mrow[4], lrow[4], acc[4][4];
#pragma unroll
    for (int ri = 0; ri < 4; ++ri) {
        mrow[ri] = -INFINITY;
        lrow[ri] = 0.0f;
#pragma unroll
        for (int ci = 0; ci < 4; ++ci) acc[ri][ci] = 0.0f;
    }

    const float* kbase = g_k + (size_t)bh * S_ * 64;
    const float* vbase = g_v + (size_t)bh * S_ * 64;

    for (int kt = 0; kt < nkt; ++kt) {
        const int k0 = kt * 64;
        const int jb = kt >> 2;           // key block (0..7)
        __syncthreads();                  // prior PV done before overwriting tiles
        {
            int key = tid >> 2;
            int dseg = (tid & 3) << 4;
            const float* kp = kbase + (size_t)(k0 + key) * 64 + dseg;
            const float* vp = vbase + (size_t)(k0 + key) * 64 + dseg;
#pragma unroll
            for (int i = 0; i < 4; ++i) {
                float4 kv = *(const float4*)(kp + i * 4);
                int d = dseg + i * 4;
                KP[(d + 0) * 64 + key] = kv.x;
                KP[(d + 1) * 64 + key] = kv.y;
                KP[(d + 2) * 64 + key] = kv.z;
                KP[(d + 3) * 64 + key] = kv.w;
                *(float4*)(Vs + key * 64 + d) = *(const float4*)(vp + i * 4);
            }
        }
        __syncthreads();

        // Scores: S = Q K^T over d
        float s[4][4];
#pragma unroll
        for (int ri = 0; ri < 4; ++ri)
#pragma unroll
            for (int ci = 0; ci < 4; ++ci) s[ri][ci] = 0.0f;
#pragma unroll 4
        for (int d = 0; d < 64; ++d) {
            float4 aq = *(const float4*)(Qs + d * 64 + (ty << 2));
            float4 bk = *(const float4*)(KP + d * 64 + (tx << 2));
            float a[4] = {aq.x, aq.y, aq.z, aq.w};
            float bb[4] = {bk.x, bk.y, bk.z, bk.w};
#pragma unroll
            for (int ri = 0; ri < 4; ++ri)
#pragma unroll
                for (int ci = 0; ci < 4; ++ci)
                    s[ri][ci] = fmaf(a[ri], bb[ci], s[ri][ci]);
        }
        __syncthreads();   // everyone done reading KP before writing P into it

        // Mask + online softmax, write P into KP
#pragma unroll
        for (int ri = 0; ri < 4; ++ri) {
            const int qrow = q0 + ty * 4 + ri;
            const bool sel = (msk[ri] >> jb) & 1u;
            float mx = -INFINITY;
#pragma unroll
            for (int ci = 0; ci < 4; ++ci) {
                int kg = k0 + tx * 4 + ci;
                bool valid = sel && (jb != cur || kg <= qrow);
                float sv = valid ? s[ri][ci] * 0.125f : -INFINITY;
                s[ri][ci] = sv;
                mx = fmaxf(mx, sv);
            }
#pragma unroll
            for (int off = 8; off >= 1; off >>= 1)
                mx = fmaxf(mx, __shfl_xor_sync(0xffffffffu, mx, off, 16));
            float newm = fmaxf(mrow[ri], mx);
            float fac;
            if (mrow[ri] == -INFINITY)
                fac = (newm == -INFINITY) ? 1.0f : 0.0f;
            else
                fac = __expf(mrow[ri] - newm);
            float rs = 0.0f;
#pragma unroll
            for (int ci = 0; ci < 4; ++ci) {
                float pv = (s[ri][ci] == -INFINITY) ? 0.0f : __expf(s[ri][ci] - newm);
                KP[(ty * 4 + ri) * 64 + tx * 4 + ci] = pv;
                rs += pv;
            }
#pragma unroll
            for (int off = 8; off >= 1; off >>= 1)
                rs += __shfl_xor_sync(0xffffffffu, rs, off, 16);
            lrow[ri] = lrow[ri] * fac + rs;
            mrow[ri] = newm;
#pragma unroll
            for (int ci = 0; ci < 4; ++ci) acc[ri][ci] *= fac;
        }
        __syncthreads();

        // acc += P @ V
#pragma unroll 4
        for (int kk = 0; kk < 64; ++kk) {
            float4 vv = *(const float4*)(Vs + kk * 64 + (tx << 2));
            float p0 = KP[(ty * 4 + 0) * 64 + kk];
            float p1 = KP[(ty * 4 + 1) * 64 + kk];
            float p2 = KP[(ty * 4 + 2) * 64 + kk];
            float p3 = KP[(ty * 4 + 3) * 64 + kk];
            acc[0][0] = fmaf(p0, vv.x, acc[0][0]);
            acc[0][1] = fmaf(p0, vv.y, acc[0][1]);
            acc[0][2] = fmaf(p0, vv.z, acc[0][2]);
            acc[0][3] = fmaf(p0, vv.w, acc[0][3]);
            acc[1][0] = fmaf(p1, vv.x, acc[1][0]);
            acc[1][1] = fmaf(p1, vv.y, acc[1][1]);
            acc[1][2] = fmaf(p1, vv.z, acc[1][2]);
            acc[1][3] = fmaf(p1, vv.w, acc[1][3]);
            acc[2][0] = fmaf(p2, vv.x, acc[2][0]);
            acc[2][1] = fmaf(p2, vv.y, acc[2][1]);
            acc[2][2] = fmaf(p2, vv.z, acc[2][2]);
            acc[2][3] = fmaf(p2, vv.w, acc[2][3]);
            acc[3][0] = fmaf(p3, vv.x, acc[3][0]);
            acc[3][1] = fmaf(p3, vv.y, acc[3][1]);
            acc[3][2] = fmaf(p3, vv.z, acc[3][2]);
            acc[3][3] = fmaf(p3, vv.w, acc[3][3]);
        }
    }

    // Epilogue: normalize and write to (b, s, h, d) layout
#pragma unroll
    for (int ri = 0; ri < 4; ++ri) {
        int qrow = q0 + ty * 4 + ri;
        float inv = 1.0f / lrow[ri];
        float4 o = make_float4(acc[ri][0] * inv, acc[ri][1] * inv,
                               acc[ri][2] * inv, acc[ri][3] * inv);
        *(float4*)(g_attn + ((size_t)(b * S_ + qrow) * H_ + h) * 64 + (tx << 2)) = o;
    }
}

// ---------------------------------------------------------------------------
extern "C" void kernel_launch(void* const* d_in, const int* in_sizes, int n_in,
                              void* d_out, int out_size) {
    const float* hidden = (const float*)d_in[0];
    const float* Wq = (const float*)d_in[1];
    const float* Wk = (const float*)d_in[2];
    const float* Wv = (const float*)d_in[3];
    const float* Wo = (const float*)d_in[4];

    dim3 ggrid(HID_ / 128, M_ / 128);   // (6, 32)

    gemm_kernel<<<ggrid, 256>>>(hidden, Wq, nullptr, 0);
    gemm_kernel<<<ggrid, 256>>>(hidden, Wk, nullptr, 1);
    gemm_kernel<<<ggrid, 256>>>(hidden, Wv, nullptr, 2);

    rope_kernel<<<(2 * B_ * H_ * S_ * 32 + 255) / 256, 256>>>();
    brep_kernel<<<B_ * H_ * NB_, 64>>>();
    select_kernel<<<B_ * H_ * S_ / 128, 128>>>();

    attn_kernel<<<dim3(S_ / 64, H_, B_), 256, 48 * 1024>>>();

    gemm_kernel<<<ggrid, 256>>>(nullptr, Wo, (float*)d_out, 3);
}

// round 4
// speedup vs baseline: 1.2073x; 1.2073x over previous
#include <cuda_runtime.h>
#include <cuda_bf16.h>
#include <math.h>
#include <float.h>

// Problem constants
#define B_   2
#define S_   2048
#define HID_ 768
#define H_   12
#define D_   64
#define BS_  256
#define NB_  8
#define TK_  3
#define M_   (B_ * S_)          // 4096 token rows

// Scratch (device globals; no runtime allocation allowed)
__device__ float g_q[B_ * H_ * S_ * D_];
__device__ float g_k[B_ * H_ * S_ * D_];
__device__ float g_v[B_ * H_ * S_ * D_];
__device__ float g_attn[B_ * S_ * HID_];
__device__ float g_brep[B_ * H_ * NB_ * D_];
__device__ unsigned char g_mask[B_ * H_ * S_];
__device__ float g_invf[32];

// ---------------------------------------------------------------------------
// Packed f32x2 helpers (Blackwell FFMA2 — 2x fp32 FMA throughput, exact IEEE)
// ---------------------------------------------------------------------------
typedef unsigned long long u64t;

__device__ __forceinline__ u64t f2_pack(float lo, float hi) {
    u64t r; asm("mov.b64 %0, {%1,%2};" : "=l"(r) : "f"(lo), "f"(hi)); return r;
}
__device__ __forceinline__ u64t f2_dup(float x) { return f2_pack(x, x); }
__device__ __forceinline__ void f2_unpack(u64t v, float& lo, float& hi) {
    asm("mov.b64 {%0,%1}, %2;" : "=f"(lo), "=f"(hi) : "l"(v));
}
__device__ __forceinline__ u64t f2_fma(u64t a, u64t b, u64t c) {
    u64t d; asm("fma.rn.f32x2 %0, %1, %2, %3;" : "=l"(d) : "l"(a), "l"(b), "l"(c));
    return d;
}
__device__ __forceinline__ u64t f2_mul(u64t a, u64t b) {
    u64t d; asm("mul.rn.f32x2 %0, %1, %2;" : "=l"(d) : "l"(a), "l"(b));
    return d;
}

// ---------------------------------------------------------------------------
// GEMM: C[M,N] = A[M,K] * W[N,K]^T  (fp32, 128x128 tile, BK=16, 8x8 microtile,
// packed f32x2 inner loop).  MODE 0: QKV fused via blockIdx.z, permuted
// epilogue into (b,h,s,d), A = external hidden_states.
// MODE 1: O-projection, A = g_attn (resolved in DEVICE code), row-major out.
// ---------------------------------------------------------------------------
template <int MODE>
__global__ __launch_bounds__(256) void gemm_kernel(
    const float* __restrict__ Aext,
    const float* __restrict__ W0, const float* __restrict__ W1,
    const float* __restrict__ W2, float* __restrict__ out) {
    const int K = HID_;
    __shared__ float As[16][128];
    __shared__ float Bs[16][128];

    const float* A;
    const float* W;
    float* dst;
    if (MODE == 0) {
        A   = Aext;
        W   = (blockIdx.z == 0) ? W0 : (blockIdx.z == 1) ? W1 : W2;
        dst = (blockIdx.z == 0) ? g_q : (blockIdx.z == 1) ? g_k : g_v;
    } else {
        A = g_attn;      // device-global resolved in device code (host address is invalid!)
        W = W0;
        dst = out;
    }

    const int bm = blockIdx.y * 128;
    const int bn = blockIdx.x * 128;
    const int tid = threadIdx.x;
    const int ty = tid >> 4;       // 0..15
    const int tx = tid & 15;       // 0..15

    const int lr = tid >> 1;       // 0..127 (tile row for loads)
    const int lk = (tid & 1) * 8;  // 0 or 8

    u64t acc2[4][8];               // row-pairs (2p,2p+1) x 8 cols
#pragma unroll
    for (int p = 0; p < 4; ++p)
#pragma unroll
        for (int j = 0; j < 8; ++j) acc2[p][j] = 0ull;

    const float* aptr = A + (size_t)(bm + lr) * K + lk;
    const float* bptr = W + (size_t)(bn + lr) * K + lk;

    for (int k0 = 0; k0 < K; k0 += 16) {
        float4 av0 = *(const float4*)(aptr + k0);
        float4 av1 = *(const float4*)(aptr + k0 + 4);
        float4 bv0 = *(const float4*)(bptr + k0);
        float4 bv1 = *(const float4*)(bptr + k0 + 4);
        As[lk + 0][lr] = av0.x; As[lk + 1][lr] = av0.y;
        As[lk + 2][lr] = av0.z; As[lk + 3][lr] = av0.w;
        As[lk + 4][lr] = av1.x; As[lk + 5][lr] = av1.y;
        As[lk + 6][lr] = av1.z; As[lk + 7][lr] = av1.w;
        Bs[lk + 0][lr] = bv0.x; Bs[lk + 1][lr] = bv0.y;
        Bs[lk + 2][lr] = bv0.z; Bs[lk + 3][lr] = bv0.w;
        Bs[lk + 4][lr] = bv1.x; Bs[lk + 5][lr] = bv1.y;
        Bs[lk + 6][lr] = bv1.z; Bs[lk + 7][lr] = bv1.w;
        __syncthreads();
#pragma unroll
        for (int k = 0; k < 16; ++k) {
            ulonglong2 a01 = *(const ulonglong2*)&As[k][ty * 8];
            ulonglong2 a23 = *(const ulonglong2*)&As[k][ty * 8 + 4];
            u64t a2[4] = {a01.x, a01.y, a23.x, a23.y};
            float4 b0 = *(const float4*)&Bs[k][tx * 8];
            float4 b1 = *(const float4*)&Bs[k][tx * 8 + 4];
            u64t bd[8];
            bd[0] = f2_dup(b0.x); bd[1] = f2_dup(b0.y);
            bd[2] = f2_dup(b0.z); bd[3] = f2_dup(b0.w);
            bd[4] = f2_dup(b1.x); bd[5] = f2_dup(b1.y);
            bd[6] = f2_dup(b1.z); bd[7] = f2_dup(b1.w);
#pragma unroll
            for (int p = 0; p < 4; ++p)
#pragma unroll
                for (int j = 0; j < 8; ++j)
                    acc2[p][j] = f2_fma(a2[p], bd[j], acc2[p][j]);
        }
        __syncthreads();
    }

    // Epilogue
#pragma unroll
    for (int p = 0; p < 4; ++p) {
        float ra[8], rb[8];
#pragma unroll
        for (int j = 0; j < 8; ++j) f2_unpack(acc2[p][j], ra[j], rb[j]);
#pragma unroll
        for (int half = 0; half < 2; ++half) {
            const float* r = half ? rb : ra;
            int row = bm + ty * 8 + 2 * p + half;
#pragma unroll
            for (int jj = 0; jj < 2; ++jj) {
                int col = bn + tx * 8 + jj * 4;
                float4 v = make_float4(r[jj * 4 + 0], r[jj * 4 + 1],
                                       r[jj * 4 + 2], r[jj * 4 + 3]);
                if (MODE == 0) {
                    int bb = row >> 11;          // / S_
                    int ss = row & (S_ - 1);
                    int hh = col >> 6;           // / D_
                    int dd = col & 63;
                    *(float4*)(dst + (((size_t)(bb * H_ + hh) * S_ + ss) << 6) + dd) = v;
                } else {
                    *(float4*)(dst + (size_t)row * HID_ + col) = v;
                }
            }
        }
    }
}

// ---------------------------------------------------------------------------
// inv_freq table (double-precision, computed once — bit-identical to ref path)
// ---------------------------------------------------------------------------
__global__ void init_invf_kernel() {
    int i = threadIdx.x;
    if (i < 32) g_invf[i] = (float)exp(-9.210340371976184 * (double)i / 32.0);
}

// ---------------------------------------------------------------------------
// RoPE in-place on g_q and g_k.  One thread per (tensor, row, pair i<32).
// ---------------------------------------------------------------------------
__global__ __launch_bounds__(256) void rope_kernel() {
    const int PER = B_ * H_ * S_ * 32;   // 1,572,864
    int idx = blockIdx.x * 256 + threadIdx.x;
    if (idx >= 2 * PER) return;
    float* base = (idx < PER) ? g_q : g_k;
    int r = (idx < PER) ? idx : idx - PER;
    int i = r & 31;
    int rowid = r >> 5;
    int s = rowid & (S_ - 1);
    float inv = g_invf[i];
    float ang = (float)s * inv;
    float c = cosf(ang);
    float sn = sinf(ang);
    float* p = base + (size_t)rowid * 64;
    float x1 = p[i];
    float x2 = p[i + 32];
    p[i]      = x1 * c - x2 * sn;
    p[i + 32] = x2 * c + x1 * sn;
}

// ---------------------------------------------------------------------------
// Block representatives: mean of (roped) K over each 256-token block.
// ---------------------------------------------------------------------------
__global__ __launch_bounds__(64) void brep_kernel() {
    int blk = blockIdx.x;          // bh*8 + nb
    int bh = blk >> 3;
    int nbk = blk & 7;
    int d = threadIdx.x;
    const float* kp = g_k + ((size_t)bh * S_ + nbk * BS_) * 64 + d;
    float sum = 0.0f;
    for (int i = 0; i < BS_; ++i) sum += kp[(size_t)i * 64];
    g_brep[(size_t)blk * 64 + d] = sum * (1.0f / 256.0f);
}

// ---------------------------------------------------------------------------
// Top-3 block selection per query (jax.lax.top_k tie-break semantics).
// ---------------------------------------------------------------------------
__global__ __launch_bounds__(128) void select_kernel() {
    __shared__ float Qsh[128 * 65];
    __shared__ float Bsh[NB_ * 64];
    const int tid = threadIdx.x;
    const size_t qbase = (size_t)blockIdx.x * 128;   // linear (b,h,s) index
    const int bh = (int)(qbase >> 11);

    for (int off = tid; off < NB_ * 64; off += 128)
        Bsh[off] = g_brep[(size_t)bh * (NB_ * 64) + off];
    const float* qp = g_q + qbase * 64;
    for (int off = tid; off < 128 * 64; off += 128)
        Qsh[(off >> 6) * 65 + (off & 63)] = qp[off];
    __syncthreads();

    int qidx = (int)qbase + tid;
    int s = qidx & (S_ - 1);
    int cur = s >> 8;
    const float* qr = Qsh + tid * 65;

    float sc[NB_];
#pragma unroll
    for (int j = 0; j < NB_; ++j) {
        if (j > cur) { sc[j] = -INFINITY; continue; }
        if (j == cur) { sc[j] = 3.402823466e38f; continue; }
        float dd = 0.0f;
#pragma unroll 8
        for (int d = 0; d < 64; ++d) dd = fmaf(qr[d], Bsh[j * 64 + d], dd);
        sc[j] = dd;
    }

    unsigned msk = 0;
    bool used[NB_];
#pragma unroll
    for (int j = 0; j < NB_; ++j) used[j] = false;
#pragma unroll
    for (int t = 0; t < TK_; ++t) {
        int bi = -1; float bv = 0.0f;
#pragma unroll
        for (int j = 0; j < NB_; ++j) {
            if (!used[j] && (bi < 0 || sc[j] > bv)) { bi = j; bv = sc[j]; }
        }
        used[bi] = true;
        msk |= 1u << bi;
    }
    g_mask[qidx] = (unsigned char)msk;
}

// ---------------------------------------------------------------------------
// Sparse flash attention.  grid = (S/64, H, B), 256 threads.
// f32x2-packed QK and PV loops.
// ---------------------------------------------------------------------------
__global__ __launch_bounds__(256) void attn_kernel() {
    extern __shared__ float sm[];
    float* Qs = sm;            // [64][64] layout [d][m]
    float* KP = sm + 4096;     // K tile [d][key], later P [row][key]
    float* Vs = sm + 8192;     // [key][d]

    const int qt = blockIdx.x, h = blockIdx.y, b = blockIdx.z;
    const int q0 = qt * 64;
    const int tid = threadIdx.x;
    const int ty = tid >> 4, tx = tid & 15;
    const int bh = b * H_ + h;

    // Load Q tile transposed into [d][m]
    {
        int m = tid >> 2;
        int dseg = (tid & 3) << 4;
        const float* p = g_q + ((size_t)bh * S_ + q0 + m) * 64 + dseg;
#pragma unroll
        for (int i = 0; i < 4; ++i) {
            float4 v = *(const float4*)(p + i * 4);
            int d = dseg + i * 4;
            Qs[(d + 0) * 64 + m] = v.x;
            Qs[(d + 1) * 64 + m] = v.y;
            Qs[(d + 2) * 64 + m] = v.z;
            Qs[(d + 3) * 64 + m] = v.w;
        }
    }

    const int cur = q0 >> 8;
    const int nkt = ((cur >= 2) ? (cur + 1) : 3) * 4;   // key tiles of 64

    unsigned msk[4];
#pragma unroll
    for (int ri = 0; ri < 4; ++ri)
        msk[ri] = g_mask[(size_t)bh * S_ + q0 + ty * 4 + ri];

    float mrow[4], lrow[4];
    u64t acc2[4][2];           // cols paired: (tx*4+0,1),(tx*4+2,3)
#pragma unroll
    for (int ri = 0; ri < 4; ++ri) {
        mrow[ri] = -INFINITY;
        lrow[ri] = 0.0f;
        acc2[ri][0] = 0ull;
        acc2[ri][1] = 0ull;
    }

    const float* kbase = g_k + (size_t)bh * S_ * 64;
    const float* vbase = g_v + (size_t)bh * S_ * 64;

    for (int kt = 0; kt < nkt; ++kt) {
        const int k0 = kt * 64;
        const int jb = kt >> 2;           // key block (0..7)
        __syncthreads();                  // prior PV done before overwriting tiles
        {
            int key = tid >> 2;
            int dseg = (tid & 3) << 4;
            const float* kp = kbase + (size_t)(k0 + key) * 64 + dseg;
            const float* vp = vbase + (size_t)(k0 + key) * 64 + dseg;
#pragma unroll
            for (int i = 0; i < 4; ++i) {
                float4 kv = *(const float4*)(kp + i * 4);
                int d = dseg + i * 4;
                KP[(d + 0) * 64 + key] = kv.x;
                KP[(d + 1) * 64 + key] = kv.y;
                KP[(d + 2) * 64 + key] = kv.z;
                KP[(d + 3) * 64 + key] = kv.w;
                *(float4*)(Vs + key * 64 + d) = *(const float4*)(vp + i * 4);
            }
        }
        __syncthreads();

        // Scores: S = Q K^T over d  (f32x2 packed over key-cols)
        u64t s2[4][2];
#pragma unroll
        for (int ri = 0; ri < 4; ++ri) { s2[ri][0] = 0ull; s2[ri][1] = 0ull; }
#pragma unroll 4
        for (int d = 0; d < 64; ++d) {
            float4 aq = *(const float4*)(Qs + d * 64 + (ty << 2));
            ulonglong2 bk = *(const ulonglong2*)(KP + d * 64 + (tx << 2));
            u64t ad[4] = {f2_dup(aq.x), f2_dup(aq.y), f2_dup(aq.z), f2_dup(aq.w)};
#pragma unroll
            for (int ri = 0; ri < 4; ++ri) {
                s2[ri][0] = f2_fma(ad[ri], bk.x, s2[ri][0]);
                s2[ri][1] = f2_fma(ad[ri], bk.y, s2[ri][1]);
            }
        }
        __syncthreads();   // everyone done reading KP before writing P into it

        // Mask + online softmax, write P into KP
#pragma unroll
        for (int ri = 0; ri < 4; ++ri) {
            float s[4];
            f2_unpack(s2[ri][0], s[0], s[1]);
            f2_unpack(s2[ri][1], s[2], s[3]);
            const int qrow = q0 + ty * 4 + ri;
            const bool sel = (msk[ri] >> jb) & 1u;
            float mx = -INFINITY;
#pragma unroll
            for (int ci = 0; ci < 4; ++ci) {
                int kg = k0 + tx * 4 + ci;
                bool valid = sel && (jb != cur || kg <= qrow);
                float sv = valid ? s[ci] * 0.125f : -INFINITY;
                s[ci] = sv;
                mx = fmaxf(mx, sv);
            }
#pragma unroll
            for (int off = 8; off >= 1; off >>= 1)
                mx = fmaxf(mx, __shfl_xor_sync(0xffffffffu, mx, off, 16));
            float newm = fmaxf(mrow[ri], mx);
            float fac;
            if (mrow[ri] == -INFINITY)
                fac = (newm == -INFINITY) ? 1.0f : 0.0f;
            else
                fac = __expf(mrow[ri] - newm);
            float rs = 0.0f;
#pragma unroll
            for (int ci = 0; ci < 4; ++ci) {
                float pv = (s[ci] == -INFINITY) ? 0.0f : __expf(s[ci] - newm);
                KP[(ty * 4 + ri) * 64 + tx * 4 + ci] = pv;
                rs += pv;
            }
#pragma unroll
            for (int off = 8; off >= 1; off >>= 1)
                rs += __shfl_xor_sync(0xffffffffu, rs, off, 16);
            lrow[ri] = lrow[ri] * fac + rs;
            mrow[ri] = newm;
            u64t facd = f2_dup(fac);
            acc2[ri][0] = f2_mul(acc2[ri][0], facd);
            acc2[ri][1] = f2_mul(acc2[ri][1], facd);
        }
        __syncthreads();

        // acc += P @ V  (f32x2 packed over d-cols)
#pragma unroll 4
        for (int kk = 0; kk < 64; ++kk) {
            ulonglong2 vv = *(const ulonglong2*)(Vs + kk * 64 + (tx << 2));
            u64t p0 = f2_dup(KP[(ty * 4 + 0) * 64 + kk]);
            u64t p1 = f2_dup(KP[(ty * 4 + 1) * 64 + kk]);
            u64t p2 = f2_dup(KP[(ty * 4 + 2) * 64 + kk]);
            u64t p3 = f2_dup(KP[(ty * 4 + 3) * 64 + kk]);
            acc2[0][0] = f2_fma(p0, vv.x, acc2[0][0]);
            acc2[0][1] = f2_fma(p0, vv.y, acc2[0][1]);
            acc2[1][0] = f2_fma(p1, vv.x, acc2[1][0]);
            acc2[1][1] = f2_fma(p1, vv.y, acc2[1][1]);
            acc2[2][0] = f2_fma(p2, vv.x, acc2[2][0]);
            acc2[2][1] = f2_fma(p2, vv.y, acc2[2][1]);
            acc2[3][0] = f2_fma(p3, vv.x, acc2[3][0]);
            acc2[3][1] = f2_fma(p3, vv.y, acc2[3][1]);
        }
    }

    // Epilogue: normalize and write to (b, s, h, d) layout
#pragma unroll
    for (int ri = 0; ri < 4; ++ri) {
        int qrow = q0 + ty * 4 + ri;
        float inv = 1.0f / lrow[ri];
        float a0, a1, a2, a3;
        f2_unpack(acc2[ri][0], a0, a1);
        f2_unpack(acc2[ri][1], a2, a3);
        float4 o = make_float4(a0 * inv, a1 * inv, a2 * inv, a3 * inv);
        *(float4*)(g_attn + ((size_t)(b * S_ + qrow) * H_ + h) * 64 + (tx << 2)) = o;
    }
}

// ---------------------------------------------------------------------------
extern "C" void kernel_launch(void* const* d_in, const int* in_sizes, int n_in,
                              void* d_out, int out_size) {
    const float* hidden = (const float*)d_in[0];
    const float* Wq = (const float*)d_in[1];
    const float* Wk = (const float*)d_in[2];
    const float* Wv = (const float*)d_in[3];
    const float* Wo = (const float*)d_in[4];

    init_invf_kernel<<<1, 32>>>();

    dim3 qkv_grid(HID_ / 128, M_ / 128, 3);   // (6, 32, 3)
    gemm_kernel<0><<<qkv_grid, 256>>>(hidden, Wq, Wk, Wv, nullptr);

    rope_kernel<<<(2 * B_ * H_ * S_ * 32 + 255) / 256, 256>>>();
    brep_kernel<<<B_ * H_ * NB_, 64>>>();
    select_kernel<<<B_ * H_ * S_ / 128, 128>>>();

    attn_kernel<<<dim3(S_ / 64, H_, B_), 256, 48 * 1024>>>();

    dim3 o_grid(HID_ / 128, M_ / 128);        // (6, 32)
    gemm_kernel<1><<<o_grid, 256>>>(nullptr, Wo, nullptr, nullptr, (float*)d_out);
}

// round 6
// speedup vs baseline: 1.7148x; 1.4203x over previous
#include <cuda_runtime.h>
#include <cuda_bf16.h>
#include <math.h>
#include <float.h>
#include <stdint.h>

// Problem constants
#define B_   2
#define S_   2048
#define HID_ 768
#define H_   12
#define D_   64
#define BS_  256
#define NB_  8
#define TK_  3
#define M_   (B_ * S_)          // 4096 token rows
#define NCHUNK_ 12              // 768 / 64 K-chunks

// Scratch (device globals; no runtime allocation allowed)
__device__ float g_q[B_ * H_ * S_ * D_];
__device__ float g_k[B_ * H_ * S_ * D_];
__device__ float g_v[B_ * H_ * S_ * D_];
__device__ float g_attn[B_ * S_ * HID_];
__device__ float g_brep[B_ * H_ * NB_ * D_];
__device__ unsigned char g_mask[B_ * H_ * S_];
__device__ float g_invf[32];

// bf16 split operands in pre-swizzled tile layout:
//  tile = 128 rows x 64 cols bf16 (= 16KB, SW128 swizzled, K-major)
//  tile index = mtile * 12 + kchunk
__device__ __nv_bfloat16 g_ah[M_ * HID_];       // A hi (hidden, later attn out)
__device__ __nv_bfloat16 g_al[M_ * HID_];       // A lo
__device__ __nv_bfloat16 g_wh[4][HID_ * HID_];  // Wq,Wk,Wv,Wo hi
__device__ __nv_bfloat16 g_wl[4][HID_ * HID_];  // lo

typedef unsigned long long u64t;

__device__ __forceinline__ uint32_t smem_u32(const void* p) {
    uint32_t a;
    asm("{ .reg .u64 t; cvta.to.shared.u64 t, %1; cvt.u32.u64 %0, t; }"
        : "=r"(a) : "l"(p));
    return a;
}
__device__ __forceinline__ uint32_t sw128(uint32_t off) {
    return off ^ ((off >> 3) & 0x70);
}

// ---------------------------------------------------------------------------
// HMMA helpers (portable mma.sync path; compute_103-safe)
// ---------------------------------------------------------------------------
__device__ __forceinline__ void ldmatrix_x4(uint32_t& r0, uint32_t& r1,
                                            uint32_t& r2, uint32_t& r3,
                                            uint32_t addr) {
    asm volatile("ldmatrix.sync.aligned.m8n8.x4.shared.b16 {%0,%1,%2,%3}, [%4];"
                 : "=r"(r0), "=r"(r1), "=r"(r2), "=r"(r3) : "r"(addr));
}
__device__ __forceinline__ void mma16816(float* c, const uint32_t* a,
                                         uint32_t b0, uint32_t b1) {
    asm volatile(
        "mma.sync.aligned.m16n8k16.row.col.f32.bf16.bf16.f32 "
        "{%0,%1,%2,%3}, {%4,%5,%6,%7}, {%8,%9}, {%0,%1,%2,%3};"
        : "+f"(c[0]), "+f"(c[1]), "+f"(c[2]), "+f"(c[3])
        : "r"(a[0]), "r"(a[1]), "r"(a[2]), "r"(a[3]), "r"(b0), "r"(b1));
}

// ---------------------------------------------------------------------------
// Packed f32x2 helpers (scalar attention path)
// ---------------------------------------------------------------------------
__device__ __forceinline__ u64t f2_pack(float lo, float hi) {
    u64t r; asm("mov.b64 %0, {%1,%2};" : "=l"(r) : "f"(lo), "f"(hi)); return r;
}
__device__ __forceinline__ u64t f2_dup(float x) { return f2_pack(x, x); }
__device__ __forceinline__ void f2_unpack(u64t v, float& lo, float& hi) {
    asm("mov.b64 {%0,%1}, %2;" : "=f"(lo), "=f"(hi) : "l"(v));
}
__device__ __forceinline__ u64t f2_fma(u64t a, u64t b, u64t c) {
    u64t d; asm("fma.rn.f32x2 %0, %1, %2, %3;" : "=l"(d) : "l"(a), "l"(b), "l"(c));
    return d;
}
__device__ __forceinline__ u64t f2_mul(u64t a, u64t b) {
    u64t d; asm("mul.rn.f32x2 %0, %1, %2;" : "=l"(d) : "l"(a), "l"(b));
    return d;
}

// ---------------------------------------------------------------------------
// Convert fp32 matrix [R][768] -> bf16 hi/lo in pre-swizzled tile layout.
// dst_sel: 0 = (g_ah,g_al) from src; 1..4 = g_wh/g_wl[sel-1] from src;
//          5 = (g_ah,g_al) from g_attn (device global).
// ---------------------------------------------------------------------------
__global__ __launch_bounds__(256) void convert_split_kernel(
    const float* __restrict__ src_p, int dst_sel, int R) {
    int idx = blockIdx.x * 256 + threadIdx.x;
    int total = R * (HID_ / 2);
    if (idx >= total) return;
    const float* src = (dst_sel == 5) ? g_attn : src_p;
    __nv_bfloat16* dh;
    __nv_bfloat16* dl;
    if (dst_sel == 0 || dst_sel == 5) { dh = g_ah; dl = g_al; }
    else { dh = g_wh[dst_sel - 1]; dl = g_wl[dst_sel - 1]; }

    int rg  = idx / (HID_ / 2);
    int col = (idx - rg * (HID_ / 2)) * 2;
    int mtile = rg >> 7;
    int r = rg & 127;
    int chunk = col >> 6;
    int cc = col & 63;
    uint32_t boff = (uint32_t)(r * 128 + cc * 2);
    uint32_t sw = sw128(boff);
    size_t dst_half = (size_t)(mtile * NCHUNK_ + chunk) * 8192 + (sw >> 1);

    float2 v = *(const float2*)(src + (size_t)rg * HID_ + col);
    __nv_bfloat16 h0 = __float2bfloat16(v.x);
    __nv_bfloat16 h1 = __float2bfloat16(v.y);
    __nv_bfloat16 l0 = __float2bfloat16(v.x - __bfloat162float(h0));
    __nv_bfloat16 l1 = __float2bfloat16(v.y - __bfloat162float(h1));
    *(__nv_bfloat162*)(dh + dst_half) = __nv_bfloat162(h0, h1);
    *(__nv_bfloat162*)(dl + dst_half) = __nv_bfloat162(l0, l1);
}

// ---------------------------------------------------------------------------
// HMMA GEMM: C[128x128 tile] = A * W^T, bf16x3 error-compensated split.
// 256 threads = 8 warps, warp tile 32x64 (4x2 warp grid).
// MODE 0: A = hidden split, W = g_wh/g_wl[z], permute epilogue into g_q/g_k/g_v
// MODE 1: A = attn split,   W = g_wh/g_wl[3], row-major into out
// smem: 4 pre-swizzled 16KB tiles (Ah, Al, Bh, Bl).
// ---------------------------------------------------------------------------
#define T_AH 0
#define T_AL 16384
#define T_BH 32768
#define T_BL 49152
#define GEMM_SMEM_BYTES 65536

template <int MODE>
__global__ __launch_bounds__(256) void mma_gemm_kernel(float* __restrict__ out) {
    extern __shared__ char smem[];
    const uint32_t sb = smem_u32(smem);
    const int tid = threadIdx.x;
    const int wid = tid >> 5, lid = tid & 31;
    const int bn = blockIdx.x;     // N tile 0..5
    const int bm = blockIdx.y;     // M tile 0..31
    const int wm = (wid & 3) * 32;
    const int wn = (wid >> 2) * 64;

    const __nv_bfloat16 *Ah, *Al, *Bh, *Bl;
    float* dst;
    if (MODE == 0) {
        int z = blockIdx.z;
        Ah = g_ah; Al = g_al; Bh = g_wh[z]; Bl = g_wl[z];
        dst = (z == 0) ? g_q : (z == 1) ? g_k : g_v;
    } else {
        Ah = g_ah; Al = g_al; Bh = g_wh[3]; Bl = g_wl[3];
        dst = out;
    }

    float acc[2][8][4];            // [m16 block][n8 block][c-frag]
#pragma unroll
    for (int i = 0; i < 2; ++i)
#pragma unroll
        for (int j = 0; j < 8; ++j)
#pragma unroll
            for (int r = 0; r < 4; ++r) acc[i][j][r] = 0.0f;

    const size_t a_base = (size_t)bm * NCHUNK_ * 8192;
    const size_t b_base = (size_t)bn * NCHUNK_ * 8192;

    // Per-lane ldmatrix row/col components (within 128x64 tile)
    const int a_row = (lid & 15);                 // + wm + 16*i
    const int a_kc8 = (lid >> 4) << 3;            // k offset 0/8
    const int b_row = (lid & 7) + ((lid >> 4) << 3);  // + wn + 16*jp
    const int b_kc8 = ((lid >> 3) & 1) << 3;

    for (int c = 0; c < NCHUNK_; ++c) {
        if (c > 0) __syncthreads();        // compute done before overwrite
        {
            const uint4* s0 = (const uint4*)(Ah + a_base + (size_t)c * 8192);
            const uint4* s1 = (const uint4*)(Al + a_base + (size_t)c * 8192);
            const uint4* s2 = (const uint4*)(Bh + b_base + (size_t)c * 8192);
            const uint4* s3 = (const uint4*)(Bl + b_base + (size_t)c * 8192);
            uint4* d0 = (uint4*)(smem + T_AH);
            uint4* d1 = (uint4*)(smem + T_AL);
            uint4* d2 = (uint4*)(smem + T_BH);
            uint4* d3 = (uint4*)(smem + T_BL);
#pragma unroll
            for (int i = 0; i < 4; ++i) {
                int o = tid + i * 256;
                d0[o] = s0[o];
                d1[o] = s1[o];
                d2[o] = s2[o];
                d3[o] = s3[o];
            }
        }
        __syncthreads();

#pragma unroll
        for (int ks = 0; ks < 4; ++ks) {
            const int k0 = ks * 16;
            // A fragments (hi & lo), 2 m16-blocks
            uint32_t fah[2][4], fal[2][4];
#pragma unroll
            for (int i = 0; i < 2; ++i) {
                uint32_t boff = (uint32_t)((wm + 16 * i + a_row) * 128 +
                                           (k0 + a_kc8) * 2);
                uint32_t sw = sw128(boff);
                ldmatrix_x4(fah[i][0], fah[i][1], fah[i][2], fah[i][3],
                            sb + T_AH + sw);
                ldmatrix_x4(fal[i][0], fal[i][1], fal[i][2], fal[i][3],
                            sb + T_AL + sw);
            }
            // B fragments (hi & lo), 4 n16-pairs -> 8 n8-blocks
            uint32_t fbh[4][4], fbl[4][4];
#pragma unroll
            for (int jp = 0; jp < 4; ++jp) {
                uint32_t boff = (uint32_t)((wn + 16 * jp + b_row) * 128 +
                                           (k0 + b_kc8) * 2);
                uint32_t sw = sw128(boff);
                ldmatrix_x4(fbh[jp][0], fbh[jp][1], fbh[jp][2], fbh[jp][3],
                            sb + T_BH + sw);
                ldmatrix_x4(fbl[jp][0], fbl[jp][1], fbl[jp][2], fbl[jp][3],
                            sb + T_BL + sw);
            }
#pragma unroll
            for (int i = 0; i < 2; ++i)
#pragma unroll
                for (int j = 0; j < 8; ++j) {
                    int jp = j >> 1, rr = (j & 1) * 2;
                    mma16816(acc[i][j], fah[i], fbh[jp][rr], fbh[jp][rr + 1]);
                    mma16816(acc[i][j], fah[i], fbl[jp][rr], fbl[jp][rr + 1]);
                    mma16816(acc[i][j], fal[i], fbh[jp][rr], fbh[jp][rr + 1]);
                }
        }
    }

    // Epilogue: lane holds (m = g / g+8, n = 2t, 2t+1) per (i, j)
    const int g = lid >> 2, t = lid & 3;
#pragma unroll
    for (int i = 0; i < 2; ++i) {
#pragma unroll
        for (int j = 0; j < 8; ++j) {
            int row0 = bm * 128 + wm + 16 * i + g;
            int n = bn * 128 + wn + 8 * j + 2 * t;
            if (MODE == 0) {
                int hh = n >> 6, dd = n & 63;
#pragma unroll
                for (int half = 0; half < 2; ++half) {
                    int row = row0 + half * 8;
                    int bb = row >> 11;
                    int ss = row & (S_ - 1);
                    float2 v = make_float2(acc[i][j][half * 2 + 0],
                                           acc[i][j][half * 2 + 1]);
                    *(float2*)(dst + (((size_t)(bb * H_ + hh) * S_ + ss) << 6) + dd) = v;
                }
            } else {
#pragma unroll
                for (int half = 0; half < 2; ++half) {
                    int row = row0 + half * 8;
                    float2 v = make_float2(acc[i][j][half * 2 + 0],
                                           acc[i][j][half * 2 + 1]);
                    *(float2*)(dst + (size_t)row * HID_ + n) = v;
                }
            }
        }
    }
}

// ---------------------------------------------------------------------------
// inv_freq table (double-precision, computed once)
// ---------------------------------------------------------------------------
__global__ void init_invf_kernel() {
    int i = threadIdx.x;
    if (i < 32) g_invf[i] = (float)exp(-9.210340371976184 * (double)i / 32.0);
}

// ---------------------------------------------------------------------------
// RoPE in-place on g_q and g_k.
// ---------------------------------------------------------------------------
__global__ __launch_bounds__(256) void rope_kernel() {
    const int PER = B_ * H_ * S_ * 32;
    int idx = blockIdx.x * 256 + threadIdx.x;
    if (idx >= 2 * PER) return;
    float* base = (idx < PER) ? g_q : g_k;
    int r = (idx < PER) ? idx : idx - PER;
    int i = r & 31;
    int rowid = r >> 5;
    int s = rowid & (S_ - 1);
    float inv = g_invf[i];
    float ang = (float)s * inv;
    float c = cosf(ang);
    float sn = sinf(ang);
    float* p = base + (size_t)rowid * 64;
    float x1 = p[i];
    float x2 = p[i + 32];
    p[i]      = x1 * c - x2 * sn;
    p[i + 32] = x2 * c + x1 * sn;
}

// ---------------------------------------------------------------------------
// Block representatives: mean of roped K over 256-token blocks.
// ---------------------------------------------------------------------------
__global__ __launch_bounds__(256) void brep_kernel() {
    __shared__ float red[4][64];
    int blk = blockIdx.x;          // bh*8 + nb
    int bh = blk >> 3;
    int nbk = blk & 7;
    int d = threadIdx.x & 63;
    int qd = threadIdx.x >> 6;     // 0..3
    const float* kp = g_k + ((size_t)bh * S_ + nbk * BS_ + qd * 64) * 64 + d;
    float sum = 0.0f;
#pragma unroll 8
    for (int i = 0; i < 64; ++i) sum += kp[(size_t)i * 64];
    red[qd][d] = sum;
    __syncthreads();
    if (qd == 0) {
        float t = red[0][d] + red[1][d] + red[2][d] + red[3][d];
        g_brep[(size_t)blk * 64 + d] = t * (1.0f / 256.0f);
    }
}

// ---------------------------------------------------------------------------
// Top-3 block selection per query (jax.lax.top_k tie-break semantics).
// ---------------------------------------------------------------------------
__global__ __launch_bounds__(128) void select_kernel() {
    __shared__ float Qsh[128 * 65];
    __shared__ float Bsh[NB_ * 64];
    const int tid = threadIdx.x;
    const size_t qbase = (size_t)blockIdx.x * 128;
    const int bh = (int)(qbase >> 11);

    for (int off = tid; off < NB_ * 64; off += 128)
        Bsh[off] = g_brep[(size_t)bh * (NB_ * 64) + off];
    const float* qp = g_q + qbase * 64;
    for (int off = tid; off < 128 * 64; off += 128)
        Qsh[(off >> 6) * 65 + (off & 63)] = qp[off];
    __syncthreads();

    int qidx = (int)qbase + tid;
    int s = qidx & (S_ - 1);
    int cur = s >> 8;
    const float* qr = Qsh + tid * 65;

    float sc[NB_];
#pragma unroll
    for (int j = 0; j < NB_; ++j) {
        if (j > cur) { sc[j] = -INFINITY; continue; }
        if (j == cur) { sc[j] = 3.402823466e38f; continue; }
        float dd = 0.0f;
#pragma unroll 8
        for (int d = 0; d < 64; ++d) dd = fmaf(qr[d], Bsh[j * 64 + d], dd);
        sc[j] = dd;
    }

    unsigned msk = 0;
    bool used[NB_];
#pragma unroll
    for (int j = 0; j < NB_; ++j) used[j] = false;
#pragma unroll
    for (int t = 0; t < TK_; ++t) {
        int bi = -1; float bv = 0.0f;
#pragma unroll
        for (int j = 0; j < NB_; ++j) {
            if (!used[j] && (bi < 0 || sc[j] > bv)) { bi = j; bv = sc[j]; }
        }
        used[bi] = true;
        msk |= 1u << bi;
    }
    g_mask[qidx] = (unsigned char)msk;
}

// ---------------------------------------------------------------------------
// Sparse flash attention (f32x2 scalar).
// ---------------------------------------------------------------------------
__global__ __launch_bounds__(256) void attn_kernel() {
    extern __shared__ float sm[];
    float* Qs = sm;            // [d][m]
    float* KP = sm + 4096;     // K [d][key], later P [row][key]
    float* Vs = sm + 8192;     // [key][d]

    const int qt = blockIdx.x, h = blockIdx.y, b = blockIdx.z;
    const int q0 = qt * 64;
    const int tid = threadIdx.x;
    const int ty = tid >> 4, tx = tid & 15;
    const int bh = b * H_ + h;

    {
        int m = tid >> 2;
        int dseg = (tid & 3) << 4;
        const float* p = g_q + ((size_t)bh * S_ + q0 + m) * 64 + dseg;
#pragma unroll
        for (int i = 0; i < 4; ++i) {
            float4 v = *(const float4*)(p + i * 4);
            int d = dseg + i * 4;
            Qs[(d + 0) * 64 + m] = v.x;
            Qs[(d + 1) * 64 + m] = v.y;
            Qs[(d + 2) * 64 + m] = v.z;
            Qs[(d + 3) * 64 + m] = v.w;
        }
    }

    const int cur = q0 >> 8;
    const int nkt = ((cur >= 2) ? (cur + 1) : 3) * 4;

    unsigned msk[4];
#pragma unroll
    for (int ri = 0; ri < 4; ++ri)
        msk[ri] = g_mask[(size_t)bh * S_ + q0 + ty * 4 + ri];

    float mrow[4], lrow[4];
    u64t acc2[4][2];
#pragma unroll
    for (int ri = 0; ri < 4; ++ri) {
        mrow[ri] = -INFINITY;
        lrow[ri] = 0.0f;
        acc2[ri][0] = 0ull;
        acc2[ri][1] = 0ull;
    }

    const float* kbase = g_k + (size_t)bh * S_ * 64;
    const float* vbase = g_v + (size_t)bh * S_ * 64;

    for (int kt = 0; kt < nkt; ++kt) {
        const int k0 = kt * 64;
        const int jb = kt >> 2;
        __syncthreads();
        {
            int key = tid >> 2;
            int dseg = (tid & 3) << 4;
            const float* kp = kbase + (size_t)(k0 + key) * 64 + dseg;
            const float* vp = vbase + (size_t)(k0 + key) * 64 + dseg;
#pragma unroll
            for (int i = 0; i < 4; ++i) {
                float4 kv = *(const float4*)(kp + i * 4);
                int d = dseg + i * 4;
                KP[(d + 0) * 64 + key] = kv.x;
                KP[(d + 1) * 64 + key] = kv.y;
                KP[(d + 2) * 64 + key] = kv.z;
                KP[(d + 3) * 64 + key] = kv.w;
                *(float4*)(Vs + key * 64 + d) = *(const float4*)(vp + i * 4);
            }
        }
        __syncthreads();

        u64t s2[4][2];
#pragma unroll
        for (int ri = 0; ri < 4; ++ri) { s2[ri][0] = 0ull; s2[ri][1] = 0ull; }
#pragma unroll 4
        for (int d = 0; d < 64; ++d) {
            float4 aq = *(const float4*)(Qs + d * 64 + (ty << 2));
            ulonglong2 bk = *(const ulonglong2*)(KP + d * 64 + (tx << 2));
            u64t ad[4] = {f2_dup(aq.x), f2_dup(aq.y), f2_dup(aq.z), f2_dup(aq.w)};
#pragma unroll
            for (int ri = 0; ri < 4; ++ri) {
                s2[ri][0] = f2_fma(ad[ri], bk.x, s2[ri][0]);
                s2[ri][1] = f2_fma(ad[ri], bk.y, s2[ri][1]);
            }
        }
        __syncthreads();

#pragma unroll
        for (int ri = 0; ri < 4; ++ri) {
            float s[4];
            f2_unpack(s2[ri][0], s[0], s[1]);
            f2_unpack(s2[ri][1], s[2], s[3]);
            const int qrow = q0 + ty * 4 + ri;
            const bool sel = (msk[ri] >> jb) & 1u;
            float mx = -INFINITY;
#pragma unroll
            for (int ci = 0; ci < 4; ++ci) {
                int kg = k0 + tx * 4 + ci;
                bool valid = sel && (jb != cur || kg <= qrow);
                float sv = valid ? s[ci] * 0.125f : -INFINITY;
                s[ci] = sv;
                mx = fmaxf(mx, sv);
            }
#pragma unroll
            for (int off = 8; off >= 1; off >>= 1)
                mx = fmaxf(mx, __shfl_xor_sync(0xffffffffu, mx, off, 16));
            float newm = fmaxf(mrow[ri], mx);
            float fac;
            if (mrow[ri] == -INFINITY)
                fac = (newm == -INFINITY) ? 1.0f : 0.0f;
            else
                fac = __expf(mrow[ri] - newm);
            float rs = 0.0f;
#pragma unroll
            for (int ci = 0; ci < 4; ++ci) {
                float pv = (s[ci] == -INFINITY) ? 0.0f : __expf(s[ci] - newm);
                KP[(ty * 4 + ri) * 64 + tx * 4 + ci] = pv;
                rs += pv;
            }
#pragma unroll
            for (int off = 8; off >= 1; off >>= 1)
                rs += __shfl_xor_sync(0xffffffffu, rs, off, 16);
            lrow[ri] = lrow[ri] * fac + rs;
            mrow[ri] = newm;
            u64t facd = f2_dup(fac);
            acc2[ri][0] = f2_mul(acc2[ri][0], facd);
            acc2[ri][1] = f2_mul(acc2[ri][1], facd);
        }
        __syncthreads();

#pragma unroll 4
        for (int kk = 0; kk < 64; ++kk) {
            ulonglong2 vv = *(const ulonglong2*)(Vs + kk * 64 + (tx << 2));
            u64t p0 = f2_dup(KP[(ty * 4 + 0) * 64 + kk]);
            u64t p1 = f2_dup(KP[(ty * 4 + 1) * 64 + kk]);
            u64t p2 = f2_dup(KP[(ty * 4 + 2) * 64 + kk]);
            u64t p3 = f2_dup(KP[(ty * 4 + 3) * 64 + kk]);
            acc2[0][0] = f2_fma(p0, vv.x, acc2[0][0]);
            acc2[0][1] = f2_fma(p0, vv.y, acc2[0][1]);
            acc2[1][0] = f2_fma(p1, vv.x, acc2[1][0]);
            acc2[1][1] = f2_fma(p1, vv.y, acc2[1][1]);
            acc2[2][0] = f2_fma(p2, vv.x, acc2[2][0]);
            acc2[2][1] = f2_fma(p2, vv.y, acc2[2][1]);
            acc2[3][0] = f2_fma(p3, vv.x, acc2[3][0]);
            acc2[3][1] = f2_fma(p3, vv.y, acc2[3][1]);
        }
    }

#pragma unroll
    for (int ri = 0; ri < 4; ++ri) {
        int qrow = q0 + ty * 4 + ri;
        float inv = 1.0f / lrow[ri];
        float a0, a1, a2, a3;
        f2_unpack(acc2[ri][0], a0, a1);
        f2_unpack(acc2[ri][1], a2, a3);
        float4 o = make_float4(a0 * inv, a1 * inv, a2 * inv, a3 * inv);
        *(float4*)(g_attn + ((size_t)(b * S_ + qrow) * H_ + h) * 64 + (tx << 2)) = o;
    }
}

// ---------------------------------------------------------------------------
extern "C" void kernel_launch(void* const* d_in, const int* in_sizes, int n_in,
                              void* d_out, int out_size) {
    const float* hidden = (const float*)d_in[0];
    const float* Wq = (const float*)d_in[1];
    const float* Wk = (const float*)d_in[2];
    const float* Wv = (const float*)d_in[3];
    const float* Wo = (const float*)d_in[4];

    static bool attr_done = false;
    if (!attr_done) {
        cudaFuncSetAttribute(mma_gemm_kernel<0>,
                             cudaFuncAttributeMaxDynamicSharedMemorySize,
                             GEMM_SMEM_BYTES);
        cudaFuncSetAttribute(mma_gemm_kernel<1>,
                             cudaFuncAttributeMaxDynamicSharedMemorySize,
                             GEMM_SMEM_BYTES);
        attr_done = true;
    }

    init_invf_kernel<<<1, 32>>>();

    // Split-convert inputs to bf16 hi/lo pre-swizzled tiles
    convert_split_kernel<<<(M_ * HID_ / 2 + 255) / 256, 256>>>(hidden, 0, M_);
    convert_split_kernel<<<(HID_ * HID_ / 2 + 255) / 256, 256>>>(Wq, 1, HID_);
    convert_split_kernel<<<(HID_ * HID_ / 2 + 255) / 256, 256>>>(Wk, 2, HID_);
    convert_split_kernel<<<(HID_ * HID_ / 2 + 255) / 256, 256>>>(Wv, 3, HID_);
    convert_split_kernel<<<(HID_ * HID_ / 2 + 255) / 256, 256>>>(Wo, 4, HID_);

    // QKV projections on tensor cores (HMMA)
    mma_gemm_kernel<0><<<dim3(HID_ / 128, M_ / 128, 3), 256, GEMM_SMEM_BYTES>>>(nullptr);

    rope_kernel<<<(2 * B_ * H_ * S_ * 32 + 255) / 256, 256>>>();
    brep_kernel<<<B_ * H_ * NB_, 256>>>();
    select_kernel<<<B_ * H_ * S_ / 128, 128>>>();

    attn_kernel<<<dim3(S_ / 64, H_, B_), 256, 48 * 1024>>>();

    // O projection: convert attn output, then HMMA GEMM into d_out
    convert_split_kernel<<<(M_ * HID_ / 2 + 255) / 256, 256>>>(nullptr, 5, M_);
    mma_gemm_kernel<1><<<dim3(HID_ / 128, M_ / 128), 256, GEMM_SMEM_BYTES>>>((float*)d_out);
}

// round 7
// speedup vs baseline: 2.9918x; 1.7447x over previous
#include <cuda_runtime.h>
#include <cuda_bf16.h>
#include <math.h>
#include <float.h>
#include <stdint.h>

// Problem constants
#define B_   2
#define S_   2048
#define HID_ 768
#define H_   12
#define D_   64
#define BS_  256
#define NB_  8
#define TK_  3
#define M_   (B_ * S_)          // 4096 token rows
#define NCHUNK_ 12              // 768 / 64 K-chunks

// Scratch (device globals; no runtime allocation allowed)
__device__ float g_q[B_ * H_ * S_ * D_];
__device__ float g_k[B_ * H_ * S_ * D_];
__device__ float g_v[B_ * H_ * S_ * D_];
__device__ float g_attn[B_ * S_ * HID_];
__device__ float g_brep[B_ * H_ * NB_ * D_];
__device__ unsigned char g_mask[B_ * H_ * S_];
__device__ float g_invf[32];

// bf16 split operands, pre-swizzled tiles (SW128, K-major rows of 128B)
__device__ __nv_bfloat16 g_ah[M_ * HID_];       // GEMM A hi
__device__ __nv_bfloat16 g_al[M_ * HID_];       // GEMM A lo
__device__ __nv_bfloat16 g_wh[4][HID_ * HID_];  // Wq,Wk,Wv,Wo hi
__device__ __nv_bfloat16 g_wl[4][HID_ * HID_];  // lo

// Attention operands: 64x64 tiles, tile idx = bh*32 + t64 (4096 elems/tile)
__device__ __nv_bfloat16 g_qh[B_ * H_ * S_ * D_];
__device__ __nv_bfloat16 g_ql[B_ * H_ * S_ * D_];
__device__ __nv_bfloat16 g_kh[B_ * H_ * S_ * D_];
__device__ __nv_bfloat16 g_kl[B_ * H_ * S_ * D_];
__device__ __nv_bfloat16 g_vth[B_ * H_ * S_ * D_];  // V transposed [d][key]
__device__ __nv_bfloat16 g_vtl[B_ * H_ * S_ * D_];

typedef unsigned long long u64t;

__device__ __forceinline__ uint32_t smem_u32(const void* p) {
    uint32_t a;
    asm("{ .reg .u64 t; cvta.to.shared.u64 t, %1; cvt.u32.u64 %0, t; }"
        : "=r"(a) : "l"(p));
    return a;
}
__device__ __forceinline__ uint32_t sw128(uint32_t off) {
    return off ^ ((off >> 3) & 0x70);
}

// ---------------------------------------------------------------------------
// HMMA helpers (portable mma.sync path; compute_103-safe)
// ---------------------------------------------------------------------------
__device__ __forceinline__ void ldmatrix_x4(uint32_t& r0, uint32_t& r1,
                                            uint32_t& r2, uint32_t& r3,
                                            uint32_t addr) {
    asm volatile("ldmatrix.sync.aligned.m8n8.x4.shared.b16 {%0,%1,%2,%3}, [%4];"
                 : "=r"(r0), "=r"(r1), "=r"(r2), "=r"(r3) : "r"(addr));
}
__device__ __forceinline__ void mma16816(float* c, const uint32_t* a,
                                         uint32_t b0, uint32_t b1) {
    asm volatile(
        "mma.sync.aligned.m16n8k16.row.col.f32.bf16.bf16.f32 "
        "{%0,%1,%2,%3}, {%4,%5,%6,%7}, {%8,%9}, {%0,%1,%2,%3};"
        : "+f"(c[0]), "+f"(c[1]), "+f"(c[2]), "+f"(c[3])
        : "r"(a[0]), "r"(a[1]), "r"(a[2]), "r"(a[3]), "r"(b0), "r"(b1));
}
// pack two fp32 into bf16x2 reg: lo -> low half, hi -> high half
__device__ __forceinline__ uint32_t bf16x2_pack(float lo, float hi) {
    uint32_t r;
    asm("cvt.rn.bf16x2.f32 %0, %1, %2;" : "=r"(r) : "f"(hi), "f"(lo));
    return r;
}

// ---------------------------------------------------------------------------
// Convert fp32 matrix [R][768] -> bf16 hi/lo pre-swizzled 128x64 tiles (GEMM)
// ---------------------------------------------------------------------------
__global__ __launch_bounds__(256) void convert_split_kernel(
    const float* __restrict__ src_p, int dst_sel, int R) {
    int idx = blockIdx.x * 256 + threadIdx.x;
    int total = R * (HID_ / 2);
    if (idx >= total) return;
    const float* src = (dst_sel == 5) ? g_attn : src_p;
    __nv_bfloat16* dh;
    __nv_bfloat16* dl;
    if (dst_sel == 0 || dst_sel == 5) { dh = g_ah; dl = g_al; }
    else { dh = g_wh[dst_sel - 1]; dl = g_wl[dst_sel - 1]; }

    int rg  = idx / (HID_ / 2);
    int col = (idx - rg * (HID_ / 2)) * 2;
    int mtile = rg >> 7;
    int r = rg & 127;
    int chunk = col >> 6;
    int cc = col & 63;
    uint32_t boff = (uint32_t)(r * 128 + cc * 2);
    uint32_t sw = sw128(boff);
    size_t dst_half = (size_t)(mtile * NCHUNK_ + chunk) * 8192 + (sw >> 1);

    float2 v = *(const float2*)(src + (size_t)rg * HID_ + col);
    __nv_bfloat16 h0 = __float2bfloat16(v.x);
    __nv_bfloat16 h1 = __float2bfloat16(v.y);
    __nv_bfloat16 l0 = __float2bfloat16(v.x - __bfloat162float(h0));
    __nv_bfloat16 l1 = __float2bfloat16(v.y - __bfloat162float(h1));
    *(__nv_bfloat162*)(dh + dst_half) = __nv_bfloat162(h0, h1);
    *(__nv_bfloat162*)(dl + dst_half) = __nv_bfloat162(l0, l1);
}

// ---------------------------------------------------------------------------
// Convert roped Q/K and V (fp32 bhsd) -> bf16 hi/lo 64x64 swizzled tiles.
// which 0: Q -> g_qh/g_ql;  1: K -> g_kh/g_kl;  2: V -> transposed g_vth/g_vtl
// One thread per (row, d-pair).
// ---------------------------------------------------------------------------
__global__ __launch_bounds__(256) void attn_convert_kernel() {
    const int N = B_ * H_ * S_ * 32;
    int idx = blockIdx.x * 256 + threadIdx.x;
    if (idx >= 3 * N) return;
    int which = idx / N;
    int r = idx - which * N;
    int dp = (r & 31) * 2;
    int row = r >> 5;             // bh*S + s
    int s = row & (S_ - 1);
    int bh = row >> 11;
    int t64 = s >> 6;
    int rr = s & 63;
    size_t tile = (size_t)(bh * 32 + t64) * 4096;

    if (which < 2) {
        const float* src = (which == 0) ? g_q : g_k;
        __nv_bfloat16* dh = (which == 0) ? g_qh : g_kh;
        __nv_bfloat16* dl = (which == 0) ? g_ql : g_kl;
        float2 v = *(const float2*)(src + (size_t)row * 64 + dp);
        __nv_bfloat16 h0 = __float2bfloat16(v.x);
        __nv_bfloat16 h1 = __float2bfloat16(v.y);
        __nv_bfloat16 l0 = __float2bfloat16(v.x - __bfloat162float(h0));
        __nv_bfloat16 l1 = __float2bfloat16(v.y - __bfloat162float(h1));
        uint32_t sw = sw128((uint32_t)(rr * 128 + dp * 2));
        *(__nv_bfloat162*)(dh + tile + (sw >> 1)) = __nv_bfloat162(h0, h1);
        *(__nv_bfloat162*)(dl + tile + (sw >> 1)) = __nv_bfloat162(l0, l1);
    } else {
        float2 v = *(const float2*)(g_v + (size_t)row * 64 + dp);
        float vv[2] = {v.x, v.y};
#pragma unroll
        for (int e = 0; e < 2; ++e) {
            int d = dp + e;
            __nv_bfloat16 h = __float2bfloat16(vv[e]);
            __nv_bfloat16 l = __float2bfloat16(vv[e] - __bfloat162float(h));
            uint32_t sw = sw128((uint32_t)(d * 128 + rr * 2));
            g_vth[tile + (sw >> 1)] = h;
            g_vtl[tile + (sw >> 1)] = l;
        }
    }
}

// ---------------------------------------------------------------------------
// HMMA GEMM (unchanged from round 6, passing).
// ---------------------------------------------------------------------------
#define T_AH 0
#define T_AL 16384
#define T_BH 32768
#define T_BL 49152
#define GEMM_SMEM_BYTES 65536

template <int MODE>
__global__ __launch_bounds__(256) void mma_gemm_kernel(float* __restrict__ out) {
    extern __shared__ char smem[];
    const uint32_t sb = smem_u32(smem);
    const int tid = threadIdx.x;
    const int wid = tid >> 5, lid = tid & 31;
    const int bn = blockIdx.x;
    const int bm = blockIdx.y;
    const int wm = (wid & 3) * 32;
    const int wn = (wid >> 2) * 64;

    const __nv_bfloat16 *Ah, *Al, *Bh, *Bl;
    float* dst;
    if (MODE == 0) {
        int z = blockIdx.z;
        Ah = g_ah; Al = g_al; Bh = g_wh[z]; Bl = g_wl[z];
        dst = (z == 0) ? g_q : (z == 1) ? g_k : g_v;
    } else {
        Ah = g_ah; Al = g_al; Bh = g_wh[3]; Bl = g_wl[3];
        dst = out;
    }

    float acc[2][8][4];
#pragma unroll
    for (int i = 0; i < 2; ++i)
#pragma unroll
        for (int j = 0; j < 8; ++j)
#pragma unroll
            for (int r = 0; r < 4; ++r) acc[i][j][r] = 0.0f;

    const size_t a_base = (size_t)bm * NCHUNK_ * 8192;
    const size_t b_base = (size_t)bn * NCHUNK_ * 8192;

    const int a_row = (lid & 15);
    const int a_kc8 = (lid >> 4) << 3;
    const int b_row = (lid & 7) + ((lid >> 4) << 3);
    const int b_kc8 = ((lid >> 3) & 1) << 3;

    for (int c = 0; c < NCHUNK_; ++c) {
        if (c > 0) __syncthreads();
        {
            const uint4* s0 = (const uint4*)(Ah + a_base + (size_t)c * 8192);
            const uint4* s1 = (const uint4*)(Al + a_base + (size_t)c * 8192);
            const uint4* s2 = (const uint4*)(Bh + b_base + (size_t)c * 8192);
            const uint4* s3 = (const uint4*)(Bl + b_base + (size_t)c * 8192);
            uint4* d0 = (uint4*)(smem + T_AH);
            uint4* d1 = (uint4*)(smem + T_AL);
            uint4* d2 = (uint4*)(smem + T_BH);
            uint4* d3 = (uint4*)(smem + T_BL);
#pragma unroll
            for (int i = 0; i < 4; ++i) {
                int o = tid + i * 256;
                d0[o] = s0[o];
                d1[o] = s1[o];
                d2[o] = s2[o];
                d3[o] = s3[o];
            }
        }
        __syncthreads();

#pragma unroll
        for (int ks = 0; ks < 4; ++ks) {
            const int k0 = ks * 16;
            uint32_t fah[2][4], fal[2][4];
#pragma unroll
            for (int i = 0; i < 2; ++i) {
                uint32_t boff = (uint32_t)((wm + 16 * i + a_row) * 128 +
                                           (k0 + a_kc8) * 2);
                uint32_t sw = sw128(boff);
                ldmatrix_x4(fah[i][0], fah[i][1], fah[i][2], fah[i][3],
                            sb + T_AH + sw);
                ldmatrix_x4(fal[i][0], fal[i][1], fal[i][2], fal[i][3],
                            sb + T_AL + sw);
            }
            uint32_t fbh[4][4], fbl[4][4];
#pragma unroll
            for (int jp = 0; jp < 4; ++jp) {
                uint32_t boff = (uint32_t)((wn + 16 * jp + b_row) * 128 +
                                           (k0 + b_kc8) * 2);
                uint32_t sw = sw128(boff);
                ldmatrix_x4(fbh[jp][0], fbh[jp][1], fbh[jp][2], fbh[jp][3],
                            sb + T_BH + sw);
                ldmatrix_x4(fbl[jp][0], fbl[jp][1], fbl[jp][2], fbl[jp][3],
                            sb + T_BL + sw);
            }
#pragma unroll
            for (int i = 0; i < 2; ++i)
#pragma unroll
                for (int j = 0; j < 8; ++j) {
                    int jp = j >> 1, rr = (j & 1) * 2;
                    mma16816(acc[i][j], fah[i], fbh[jp][rr], fbh[jp][rr + 1]);
                    mma16816(acc[i][j], fah[i], fbl[jp][rr], fbl[jp][rr + 1]);
                    mma16816(acc[i][j], fal[i], fbh[jp][rr], fbh[jp][rr + 1]);
                }
        }
    }

    const int g = lid >> 2, t = lid & 3;
#pragma unroll
    for (int i = 0; i < 2; ++i) {
#pragma unroll
        for (int j = 0; j < 8; ++j) {
            int row0 = bm * 128 + wm + 16 * i + g;
            int n = bn * 128 + wn + 8 * j + 2 * t;
            if (MODE == 0) {
                int hh = n >> 6, dd = n & 63;
#pragma unroll
                for (int half = 0; half < 2; ++half) {
                    int row = row0 + half * 8;
                    int bb = row >> 11;
                    int ss = row & (S_ - 1);
                    float2 v = make_float2(acc[i][j][half * 2 + 0],
                                           acc[i][j][half * 2 + 1]);
                    *(float2*)(dst + (((size_t)(bb * H_ + hh) * S_ + ss) << 6) + dd) = v;
                }
            } else {
#pragma unroll
                for (int half = 0; half < 2; ++half) {
                    int row = row0 + half * 8;
                    float2 v = make_float2(acc[i][j][half * 2 + 0],
                                           acc[i][j][half * 2 + 1]);
                    *(float2*)(dst + (size_t)row * HID_ + n) = v;
                }
            }
        }
    }
}

// ---------------------------------------------------------------------------
__global__ void init_invf_kernel() {
    int i = threadIdx.x;
    if (i < 32) g_invf[i] = (float)exp(-9.210340371976184 * (double)i / 32.0);
}

__global__ __launch_bounds__(256) void rope_kernel() {
    const int PER = B_ * H_ * S_ * 32;
    int idx = blockIdx.x * 256 + threadIdx.x;
    if (idx >= 2 * PER) return;
    float* base = (idx < PER) ? g_q : g_k;
    int r = (idx < PER) ? idx : idx - PER;
    int i = r & 31;
    int rowid = r >> 5;
    int s = rowid & (S_ - 1);
    float inv = g_invf[i];
    float ang = (float)s * inv;
    float c = cosf(ang);
    float sn = sinf(ang);
    float* p = base + (size_t)rowid * 64;
    float x1 = p[i];
    float x2 = p[i + 32];
    p[i]      = x1 * c - x2 * sn;
    p[i + 32] = x2 * c + x1 * sn;
}

__global__ __launch_bounds__(256) void brep_kernel() {
    __shared__ float red[4][64];
    int blk = blockIdx.x;
    int bh = blk >> 3;
    int nbk = blk & 7;
    int d = threadIdx.x & 63;
    int qd = threadIdx.x >> 6;
    const float* kp = g_k + ((size_t)bh * S_ + nbk * BS_ + qd * 64) * 64 + d;
    float sum = 0.0f;
#pragma unroll 8
    for (int i = 0; i < 64; ++i) sum += kp[(size_t)i * 64];
    red[qd][d] = sum;
    __syncthreads();
    if (qd == 0) {
        float t = red[0][d] + red[1][d] + red[2][d] + red[3][d];
        g_brep[(size_t)blk * 64 + d] = t * (1.0f / 256.0f);
    }
}

__global__ __launch_bounds__(128) void select_kernel() {
    __shared__ float Qsh[128 * 65];
    __shared__ float Bsh[NB_ * 64];
    const int tid = threadIdx.x;
    const size_t qbase = (size_t)blockIdx.x * 128;
    const int bh = (int)(qbase >> 11);

    for (int off = tid; off < NB_ * 64; off += 128)
        Bsh[off] = g_brep[(size_t)bh * (NB_ * 64) + off];
    const float* qp = g_q + qbase * 64;
    for (int off = tid; off < 128 * 64; off += 128)
        Qsh[(off >> 6) * 65 + (off & 63)] = qp[off];
    __syncthreads();

    int qidx = (int)qbase + tid;
    int s = qidx & (S_ - 1);
    int cur = s >> 8;
    const float* qr = Qsh + tid * 65;

    float sc[NB_];
#pragma unroll
    for (int j = 0; j < NB_; ++j) {
        if (j > cur) { sc[j] = -INFINITY; continue; }
        if (j == cur) { sc[j] = 3.402823466e38f; continue; }
        float dd = 0.0f;
#pragma unroll 8
        for (int d = 0; d < 64; ++d) dd = fmaf(qr[d], Bsh[j * 64 + d], dd);
        sc[j] = dd;
    }

    unsigned msk = 0;
    bool used[NB_];
#pragma unroll
    for (int j = 0; j < NB_; ++j) used[j] = false;
#pragma unroll
    for (int t = 0; t < TK_; ++t) {
        int bi = -1; float bv = 0.0f;
#pragma unroll
        for (int j = 0; j < NB_; ++j) {
            if (!used[j] && (bi < 0 || sc[j] > bv)) { bi = j; bv = sc[j]; }
        }
        used[bi] = true;
        msk |= 1u << bi;
    }
    g_mask[qidx] = (unsigned char)msk;
}

// ---------------------------------------------------------------------------
// Sparse flash attention on HMMA (bf16x3).  grid = (32, 12, 2), 128 threads.
// CTA = 64 queries; warp = 16 queries (m16); key tiles of 64.
// smem: Qh 8K | Ql 8K | Kh 8K | Kl 8K | Vth 8K | Vtl 8K = 48KB.
// ---------------------------------------------------------------------------
#define AT_QH 0
#define AT_QL 8192
#define AT_KH 16384
#define AT_KL 24576
#define AT_VH 32768
#define AT_VL 40960
#define ATTN_SMEM 49152

__global__ __launch_bounds__(128) void attn_kernel() {
    extern __shared__ char smem[];
    const uint32_t sb = smem_u32(smem);
    const int tid = threadIdx.x;
    const int wid = tid >> 5, lid = tid & 31;
    const int qt = blockIdx.x, h = blockIdx.y, b = blockIdx.z;
    const int q0 = qt * 64;
    const int bh = b * H_ + h;
    const int wq = wid * 16;

    // Load Q tiles (pre-swizzled identity copy)
    {
        const uint4* s0 = (const uint4*)(g_qh + (size_t)(bh * 32 + qt) * 4096);
        const uint4* s1 = (const uint4*)(g_ql + (size_t)(bh * 32 + qt) * 4096);
        uint4* d0 = (uint4*)(smem + AT_QH);
        uint4* d1 = (uint4*)(smem + AT_QL);
#pragma unroll
        for (int i = 0; i < 4; ++i) {
            int o = tid + i * 128;
            d0[o] = s0[o];
            d1[o] = s1[o];
        }
    }
    __syncthreads();

    // Q fragments (persistent in registers)
    const int a_row = lid & 15;
    const int a_k8 = (lid >> 4) << 3;
    const int b_row = (lid & 7) + ((lid >> 4) << 3);
    const int b_k8 = ((lid >> 3) & 1) << 3;
    uint32_t fqh[4][4], fql[4][4];
#pragma unroll
    for (int ks = 0; ks < 4; ++ks) {
        uint32_t sw = sw128((uint32_t)((wq + a_row) * 128 + (ks * 16 + a_k8) * 2));
        ldmatrix_x4(fqh[ks][0], fqh[ks][1], fqh[ks][2], fqh[ks][3], sb + AT_QH + sw);
        ldmatrix_x4(fql[ks][0], fql[ks][1], fql[ks][2], fql[ks][3], sb + AT_QL + sw);
    }

    const int g = lid >> 2;
    const int qq = (lid & 3) * 2;
    const int r0 = q0 + wq + g;        // query row (seq index) for c0,c1
    const int r1 = r0 + 8;             // for c2,c3
    const unsigned msk0 = g_mask[(size_t)bh * S_ + r0];
    const unsigned msk1 = g_mask[(size_t)bh * S_ + r1];

    const int cur = q0 >> 8;
    const int nkt = ((cur >= 2) ? (cur + 1) : 3) * 4;

    float mrow0 = -INFINITY, mrow1 = -INFINITY, lrow0 = 0.0f, lrow1 = 0.0f;
    float acc_o[8][4];
#pragma unroll
    for (int j = 0; j < 8; ++j)
#pragma unroll
        for (int r = 0; r < 4; ++r) acc_o[j][r] = 0.0f;

    for (int kt = 0; kt < nkt; ++kt) {
        const int k0 = kt * 64;
        const int jb = kt >> 2;
        __syncthreads();
        {
            size_t tb = (size_t)(bh * 32 + kt) * 4096;
            const uint4* s0 = (const uint4*)(g_kh + tb);
            const uint4* s1 = (const uint4*)(g_kl + tb);
            const uint4* s2 = (const uint4*)(g_vth + tb);
            const uint4* s3 = (const uint4*)(g_vtl + tb);
            uint4* d0 = (uint4*)(smem + AT_KH);
            uint4* d1 = (uint4*)(smem + AT_KL);
            uint4* d2 = (uint4*)(smem + AT_VH);
            uint4* d3 = (uint4*)(smem + AT_VL);
#pragma unroll
            for (int i = 0; i < 4; ++i) {
                int o = tid + i * 128;
                d0[o] = s0[o];
                d1[o] = s1[o];
                d2[o] = s2[o];
                d3[o] = s3[o];
            }
        }
        __syncthreads();

        // S = Q K^T (bf16x3)
        float s[8][4];
#pragma unroll
        for (int j = 0; j < 8; ++j)
#pragma unroll
            for (int r = 0; r < 4; ++r) s[j][r] = 0.0f;
#pragma unroll
        for (int ks = 0; ks < 4; ++ks) {
            uint32_t fkh[4][4], fkl[4][4];
#pragma unroll
            for (int jp = 0; jp < 4; ++jp) {
                uint32_t sw = sw128((uint32_t)((jp * 16 + b_row) * 128 +
                                               (ks * 16 + b_k8) * 2));
                ldmatrix_x4(fkh[jp][0], fkh[jp][1], fkh[jp][2], fkh[jp][3],
                            sb + AT_KH + sw);
                ldmatrix_x4(fkl[jp][0], fkl[jp][1], fkl[jp][2], fkl[jp][3],
                            sb + AT_KL + sw);
            }
#pragma unroll
            for (int j = 0; j < 8; ++j) {
                int jp = j >> 1, rr = (j & 1) * 2;
                mma16816(s[j], fqh[ks], fkh[jp][rr], fkh[jp][rr + 1]);
                mma16816(s[j], fqh[ks], fkl[jp][rr], fkl[jp][rr + 1]);
                mma16816(s[j], fql[ks], fkh[jp][rr], fkh[jp][rr + 1]);
            }
        }

        // Mask + scale + online softmax (fragment layout)
        const bool sel0 = (msk0 >> jb) & 1u;
        const bool sel1 = (msk1 >> jb) & 1u;
        float mx0 = -INFINITY, mx1 = -INFINITY;
#pragma unroll
        for (int j = 0; j < 8; ++j) {
#pragma unroll
            for (int e = 0; e < 2; ++e) {
                int kg = k0 + j * 8 + qq + e;
                bool v0 = sel0 && (jb != cur || kg <= r0);
                bool v1 = sel1 && (jb != cur || kg <= r1);
                float s0v = v0 ? s[j][e] * 0.125f : -INFINITY;
                float s1v = v1 ? s[j][2 + e] * 0.125f : -INFINITY;
                s[j][e] = s0v;
                s[j][2 + e] = s1v;
                mx0 = fmaxf(mx0, s0v);
                mx1 = fmaxf(mx1, s1v);
            }
        }
#pragma unroll
        for (int off = 1; off <= 2; off <<= 1) {
            mx0 = fmaxf(mx0, __shfl_xor_sync(0xffffffffu, mx0, off));
            mx1 = fmaxf(mx1, __shfl_xor_sync(0xffffffffu, mx1, off));
        }
        float newm0 = fmaxf(mrow0, mx0);
        float newm1 = fmaxf(mrow1, mx1);
        float fac0 = (mrow0 == -INFINITY) ? 0.0f : __expf(mrow0 - newm0);
        float fac1 = (mrow1 == -INFINITY) ? 0.0f : __expf(mrow1 - newm1);
        float rs0 = 0.0f, rs1 = 0.0f;
#pragma unroll
        for (int j = 0; j < 8; ++j) {
#pragma unroll
            for (int e = 0; e < 2; ++e) {
                float p0 = (s[j][e] == -INFINITY) ? 0.0f : __expf(s[j][e] - newm0);
                float p1 = (s[j][2 + e] == -INFINITY) ? 0.0f : __expf(s[j][2 + e] - newm1);
                s[j][e] = p0;
                s[j][2 + e] = p1;
                rs0 += p0;
                rs1 += p1;
            }
        }
#pragma unroll
        for (int off = 1; off <= 2; off <<= 1) {
            rs0 += __shfl_xor_sync(0xffffffffu, rs0, off);
            rs1 += __shfl_xor_sync(0xffffffffu, rs1, off);
        }
        lrow0 = lrow0 * fac0 + rs0;
        lrow1 = lrow1 * fac1 + rs1;
        mrow0 = newm0;
        mrow1 = newm1;
#pragma unroll
        for (int j = 0; j < 8; ++j) {
            acc_o[j][0] *= fac0;
            acc_o[j][1] *= fac0;
            acc_o[j][2] *= fac1;
            acc_o[j][3] *= fac1;
        }

        // acc_o += P V  (P from registers; V from transposed tiles)
#pragma unroll
        for (int j0 = 0; j0 < 4; ++j0) {
            const int j = 2 * j0;
            // P split hi/lo, packed into A fragments
            float h00 = __bfloat162float(__float2bfloat16(s[j][0]));
            float h01 = __bfloat162float(__float2bfloat16(s[j][1]));
            float h02 = __bfloat162float(__float2bfloat16(s[j][2]));
            float h03 = __bfloat162float(__float2bfloat16(s[j][3]));
            float h10 = __bfloat162float(__float2bfloat16(s[j + 1][0]));
            float h11 = __bfloat162float(__float2bfloat16(s[j + 1][1]));
            float h12 = __bfloat162float(__float2bfloat16(s[j + 1][2]));
            float h13 = __bfloat162float(__float2bfloat16(s[j + 1][3]));
            uint32_t ph[4], pl[4];
            ph[0] = bf16x2_pack(s[j][0], s[j][1]);
            ph[1] = bf16x2_pack(s[j][2], s[j][3]);
            ph[2] = bf16x2_pack(s[j + 1][0], s[j + 1][1]);
            ph[3] = bf16x2_pack(s[j + 1][2], s[j + 1][3]);
            pl[0] = bf16x2_pack(s[j][0] - h00, s[j][1] - h01);
            pl[1] = bf16x2_pack(s[j][2] - h02, s[j][3] - h03);
            pl[2] = bf16x2_pack(s[j + 1][0] - h10, s[j + 1][1] - h11);
            pl[3] = bf16x2_pack(s[j + 1][2] - h12, s[j + 1][3] - h13);

            uint32_t fvh[4][4], fvl[4][4];
#pragma unroll
            for (int jp = 0; jp < 4; ++jp) {
                uint32_t sw = sw128((uint32_t)((jp * 16 + b_row) * 128 +
                                               (j0 * 16 + b_k8) * 2));
                ldmatrix_x4(fvh[jp][0], fvh[jp][1], fvh[jp][2], fvh[jp][3],
                            sb + AT_VH + sw);
                ldmatrix_x4(fvl[jp][0], fvl[jp][1], fvl[jp][2], fvl[jp][3],
                            sb + AT_VL + sw);
            }
#pragma unroll
            for (int jn = 0; jn < 8; ++jn) {
                int jp = jn >> 1, rr = (jn & 1) * 2;
                mma16816(acc_o[jn], ph, fvh[jp][rr], fvh[jp][rr + 1]);
                mma16816(acc_o[jn], ph, fvl[jp][rr], fvl[jp][rr + 1]);
                mma16816(acc_o[jn], pl, fvh[jp][rr], fvh[jp][rr + 1]);
            }
        }
    }

    // Epilogue: normalize, write (b, s, h, d)
    float inv0 = 1.0f / lrow0;
    float inv1 = 1.0f / lrow1;
#pragma unroll
    for (int j = 0; j < 8; ++j) {
        int n = j * 8 + qq;
        float2 v0 = make_float2(acc_o[j][0] * inv0, acc_o[j][1] * inv0);
        float2 v1 = make_float2(acc_o[j][2] * inv1, acc_o[j][3] * inv1);
        *(float2*)(g_attn + ((size_t)(b * S_ + r0) * H_ + h) * 64 + n) = v0;
        *(float2*)(g_attn + ((size_t)(b * S_ + r1) * H_ + h) * 64 + n) = v1;
    }
}

// ---------------------------------------------------------------------------
extern "C" void kernel_launch(void* const* d_in, const int* in_sizes, int n_in,
                              void* d_out, int out_size) {
    const float* hidden = (const float*)d_in[0];
    const float* Wq = (const float*)d_in[1];
    const float* Wk = (const float*)d_in[2];
    const float* Wv = (const float*)d_in[3];
    const float* Wo = (const float*)d_in[4];

    static bool attr_done = false;
    if (!attr_done) {
        cudaFuncSetAttribute(mma_gemm_kernel<0>,
                             cudaFuncAttributeMaxDynamicSharedMemorySize,
                             GEMM_SMEM_BYTES);
        cudaFuncSetAttribute(mma_gemm_kernel<1>,
                             cudaFuncAttributeMaxDynamicSharedMemorySize,
                             GEMM_SMEM_BYTES);
        attr_done = true;
    }

    init_invf_kernel<<<1, 32>>>();

    convert_split_kernel<<<(M_ * HID_ / 2 + 255) / 256, 256>>>(hidden, 0, M_);
    convert_split_kernel<<<(HID_ * HID_ / 2 + 255) / 256, 256>>>(Wq, 1, HID_);
    convert_split_kernel<<<(HID_ * HID_ / 2 + 255) / 256, 256>>>(Wk, 2, HID_);
    convert_split_kernel<<<(HID_ * HID_ / 2 + 255) / 256, 256>>>(Wv, 3, HID_);
    convert_split_kernel<<<(HID_ * HID_ / 2 + 255) / 256, 256>>>(Wo, 4, HID_);

    mma_gemm_kernel<0><<<dim3(HID_ / 128, M_ / 128, 3), 256, GEMM_SMEM_BYTES>>>(nullptr);

    rope_kernel<<<(2 * B_ * H_ * S_ * 32 + 255) / 256, 256>>>();
    brep_kernel<<<B_ * H_ * NB_, 256>>>();
    select_kernel<<<B_ * H_ * S_ / 128, 128>>>();

    // bf16 hi/lo tiles for attention (Q, K roped; V transposed)
    attn_convert_kernel<<<(3 * B_ * H_ * S_ * 32 + 255) / 256, 256>>>();

    attn_kernel<<<dim3(S_ / 64, H_, B_), 128, ATTN_SMEM>>>();

    convert_split_kernel<<<(M_ * HID_ / 2 + 255) / 256, 256>>>(nullptr, 5, M_);
    mma_gemm_kernel<1><<<dim3(HID_ / 128, M_ / 128), 256, GEMM_SMEM_BYTES>>>((float*)d_out);
}

// round 8
// speedup vs baseline: 3.4666x; 1.1587x over previous
#include <cuda_runtime.h>
#include <cuda_bf16.h>
#include <math.h>
#include <float.h>
#include <stdint.h>

// Problem constants
#define B_   2
#define S_   2048
#define HID_ 768
#define H_   12
#define D_   64
#define BS_  256
#define NB_  8
#define TK_  3
#define M_   (B_ * S_)          // 4096 token rows
#define NCHUNK_ 12              // 768 / 64 K-chunks

// Scratch (device globals; no runtime allocation allowed)
__device__ float g_q[B_ * H_ * S_ * D_];
__device__ float g_k[B_ * H_ * S_ * D_];
__device__ float g_v[B_ * H_ * S_ * D_];
__device__ float g_attn[B_ * S_ * HID_];
__device__ float g_brep[B_ * H_ * NB_ * D_];
__device__ unsigned char g_mask[B_ * H_ * S_];
__device__ float g_sinT[S_ * 32];
__device__ float g_cosT[S_ * 32];

// bf16 split operands, pre-swizzled tiles (SW128, K-major rows of 128B)
__device__ __nv_bfloat16 g_ah[M_ * HID_];       // GEMM A hi
__device__ __nv_bfloat16 g_al[M_ * HID_];       // GEMM A lo
__device__ __nv_bfloat16 g_wh[4][HID_ * HID_];  // Wq,Wk,Wv,Wo hi
__device__ __nv_bfloat16 g_wl[4][HID_ * HID_];  // lo

// Attention operands: 64x64 tiles, tile idx = bh*32 + t64 (4096 elems/tile)
__device__ __nv_bfloat16 g_qh[B_ * H_ * S_ * D_];
__device__ __nv_bfloat16 g_ql[B_ * H_ * S_ * D_];
__device__ __nv_bfloat16 g_kh[B_ * H_ * S_ * D_];
__device__ __nv_bfloat16 g_kl[B_ * H_ * S_ * D_];
__device__ __nv_bfloat16 g_vth[B_ * H_ * S_ * D_];  // V transposed [d][key]
__device__ __nv_bfloat16 g_vtl[B_ * H_ * S_ * D_];

typedef unsigned long long u64t;

__device__ __forceinline__ uint32_t smem_u32(const void* p) {
    uint32_t a;
    asm("{ .reg .u64 t; cvta.to.shared.u64 t, %1; cvt.u32.u64 %0, t; }"
        : "=r"(a) : "l"(p));
    return a;
}
__device__ __forceinline__ uint32_t sw128(uint32_t off) {
    return off ^ ((off >> 3) & 0x70);
}
__device__ __forceinline__ void cp_async16(uint32_t saddr, const void* gptr) {
    asm volatile("cp.async.cg.shared.global [%0], [%1], 16;"
                 :: "r"(saddr), "l"(gptr));
}
#define CP_COMMIT() asm volatile("cp.async.commit_group;" ::: "memory")
#define CP_WAIT1()  asm volatile("cp.async.wait_group 1;" ::: "memory")
#define CP_WAIT0()  asm volatile("cp.async.wait_group 0;" ::: "memory")

// ---------------------------------------------------------------------------
// HMMA helpers
// ---------------------------------------------------------------------------
__device__ __forceinline__ void ldmatrix_x4(uint32_t& r0, uint32_t& r1,
                                            uint32_t& r2, uint32_t& r3,
                                            uint32_t addr) {
    asm volatile("ldmatrix.sync.aligned.m8n8.x4.shared.b16 {%0,%1,%2,%3}, [%4];"
                 : "=r"(r0), "=r"(r1), "=r"(r2), "=r"(r3) : "r"(addr));
}
__device__ __forceinline__ void mma16816(float* c, const uint32_t* a,
                                         uint32_t b0, uint32_t b1) {
    asm volatile(
        "mma.sync.aligned.m16n8k16.row.col.f32.bf16.bf16.f32 "
        "{%0,%1,%2,%3}, {%4,%5,%6,%7}, {%8,%9}, {%0,%1,%2,%3};"
        : "+f"(c[0]), "+f"(c[1]), "+f"(c[2]), "+f"(c[3])
        : "r"(a[0]), "r"(a[1]), "r"(a[2]), "r"(a[3]), "r"(b0), "r"(b1));
}
__device__ __forceinline__ uint32_t bf16x2_pack(float lo, float hi) {
    uint32_t r;
    asm("cvt.rn.bf16x2.f32 %0, %1, %2;" : "=r"(r) : "f"(hi), "f"(lo));
    return r;
}

// ---------------------------------------------------------------------------
// sin/cos tables (ang = s * invf[i], invf from double exp — matches ref path)
// ---------------------------------------------------------------------------
__global__ __launch_bounds__(256) void init_tab_kernel() {
    int idx = blockIdx.x * 256 + threadIdx.x;
    if (idx >= S_ * 32) return;
    int i = idx & 31;
    int s = idx >> 5;
    float inv = (float)exp(-9.210340371976184 * (double)i / 32.0);
    float ang = (float)s * inv;
    g_sinT[idx] = sinf(ang);
    g_cosT[idx] = cosf(ang);
}

// ---------------------------------------------------------------------------
// Merged input conversion: hidden + 4 weights -> bf16 hi/lo swizzled tiles.
// ---------------------------------------------------------------------------
#define NA_CONV (M_ * 384)
#define NW_CONV (HID_ * 384)
__global__ __launch_bounds__(256) void conv_all_kernel(
    const float* __restrict__ hidden, const float* __restrict__ W0,
    const float* __restrict__ W1, const float* __restrict__ W2,
    const float* __restrict__ W3) {
    int idx = blockIdx.x * 256 + threadIdx.x;
    if (idx >= NA_CONV + 4 * NW_CONV) return;
    const float* src;
    __nv_bfloat16 *dh, *dl;
    int li;
    if (idx < NA_CONV) {
        src = hidden; dh = g_ah; dl = g_al; li = idx;
    } else {
        int w = (idx - NA_CONV) / NW_CONV;
        li = (idx - NA_CONV) - w * NW_CONV;
        src = (w == 0) ? W0 : (w == 1) ? W1 : (w == 2) ? W2 : W3;
        dh = g_wh[w]; dl = g_wl[w];
    }
    int rg  = li / 384;
    int col = (li - rg * 384) * 2;
    int mtile = rg >> 7;
    int r = rg & 127;
    int chunk = col >> 6;
    int cc = col & 63;
    uint32_t sw = sw128((uint32_t)(r * 128 + cc * 2));
    size_t dst_half = (size_t)(mtile * NCHUNK_ + chunk) * 8192 + (sw >> 1);
    float2 v = *(const float2*)(src + (size_t)rg * HID_ + col);
    __nv_bfloat16 h0 = __float2bfloat16(v.x);
    __nv_bfloat16 h1 = __float2bfloat16(v.y);
    __nv_bfloat16 l0 = __float2bfloat16(v.x - __bfloat162float(h0));
    __nv_bfloat16 l1 = __float2bfloat16(v.y - __bfloat162float(h1));
    *(__nv_bfloat162*)(dh + dst_half) = __nv_bfloat162(h0, h1);
    *(__nv_bfloat162*)(dl + dst_half) = __nv_bfloat162(l0, l1);
}

// attn-output conversion (reads g_attn), same tile format
__global__ __launch_bounds__(256) void conv_attn_kernel() {
    int idx = blockIdx.x * 256 + threadIdx.x;
    if (idx >= NA_CONV) return;
    int rg  = idx / 384;
    int col = (idx - rg * 384) * 2;
    int mtile = rg >> 7;
    int r = rg & 127;
    int chunk = col >> 6;
    int cc = col & 63;
    uint32_t sw = sw128((uint32_t)(r * 128 + cc * 2));
    size_t dst_half = (size_t)(mtile * NCHUNK_ + chunk) * 8192 + (sw >> 1);
    float2 v = *(const float2*)(g_attn + (size_t)rg * HID_ + col);
    __nv_bfloat16 h0 = __float2bfloat16(v.x);
    __nv_bfloat16 h1 = __float2bfloat16(v.y);
    __nv_bfloat16 l0 = __float2bfloat16(v.x - __bfloat162float(h0));
    __nv_bfloat16 l1 = __float2bfloat16(v.y - __bfloat162float(h1));
    *(__nv_bfloat162*)(g_ah + dst_half) = __nv_bfloat162(h0, h1);
    *(__nv_bfloat162*)(g_al + dst_half) = __nv_bfloat162(l0, l1);
}

// V-only attention-tile conversion (transposed [d][key])
__global__ __launch_bounds__(256) void conv_v_kernel() {
    const int N = B_ * H_ * S_ * 32;
    int idx = blockIdx.x * 256 + threadIdx.x;
    if (idx >= N) return;
    int dp = (idx & 31) * 2;
    int row = idx >> 5;
    int s = row & (S_ - 1);
    int bh = row >> 11;
    size_t tile = (size_t)(bh * 32 + (s >> 6)) * 4096;
    int rr = s & 63;
    float2 v = *(const float2*)(g_v + (size_t)row * 64 + dp);
    float vv[2] = {v.x, v.y};
#pragma unroll
    for (int e = 0; e < 2; ++e) {
        int d = dp + e;
        __nv_bfloat16 h = __float2bfloat16(vv[e]);
        __nv_bfloat16 l = __float2bfloat16(vv[e] - __bfloat162float(h));
        uint32_t sw = sw128((uint32_t)(d * 128 + rr * 2));
        g_vth[tile + (sw >> 1)] = h;
        g_vtl[tile + (sw >> 1)] = l;
    }
}

// ---------------------------------------------------------------------------
// HMMA GEMM, cp.async double-buffered.
// MODE 0: QKV; RoPE fused in epilogue for z<2; writes fp32 (b,h,s,d) AND
//         (for z<2) bf16 hi/lo attention tiles.
// MODE 1: O-projection into out.
// smem: 2 stages x 64KB (AH|AL|BH|BL 16KB each).
// ---------------------------------------------------------------------------
#define T_AH 0
#define T_AL 16384
#define T_BH 32768
#define T_BL 49152
#define G_STAGE 65536
#define GEMM_SMEM_BYTES (2 * G_STAGE)

template <int MODE>
__global__ __launch_bounds__(256) void mma_gemm_kernel(float* __restrict__ out) {
    extern __shared__ char smem[];
    const uint32_t sb = smem_u32(smem);
    const int tid = threadIdx.x;
    const int wid = tid >> 5, lid = tid & 31;
    const int bn = blockIdx.x;
    const int bm = blockIdx.y;
    const int wm = (wid & 3) * 32;
    const int wn = (wid >> 2) * 64;
    const int z = (MODE == 0) ? blockIdx.z : 3;

    const __nv_bfloat16 *Ah, *Al, *Bh, *Bl;
    float* dst;
    if (MODE == 0) {
        Ah = g_ah; Al = g_al; Bh = g_wh[z]; Bl = g_wl[z];
        dst = (z == 0) ? g_q : (z == 1) ? g_k : g_v;
    } else {
        Ah = g_ah; Al = g_al; Bh = g_wh[3]; Bl = g_wl[3];
        dst = out;
    }

    float acc[2][8][4];
#pragma unroll
    for (int i = 0; i < 2; ++i)
#pragma unroll
        for (int j = 0; j < 8; ++j)
#pragma unroll
            for (int r = 0; r < 4; ++r) acc[i][j][r] = 0.0f;

    const size_t a_base = (size_t)bm * NCHUNK_ * 8192;
    const size_t b_base = (size_t)bn * NCHUNK_ * 8192;

    const int a_row = (lid & 15);
    const int a_kc8 = (lid >> 4) << 3;
    const int b_row = (lid & 7) + ((lid >> 4) << 3);
    const int b_kc8 = ((lid >> 3) & 1) << 3;

    auto issue_chunk = [&](int c, int st) {
        uint32_t base = sb + st * G_STAGE;
        const char* s0 = (const char*)(Ah + a_base + (size_t)c * 8192);
        const char* s1 = (const char*)(Al + a_base + (size_t)c * 8192);
        const char* s2 = (const char*)(Bh + b_base + (size_t)c * 8192);
        const char* s3 = (const char*)(Bl + b_base + (size_t)c * 8192);
#pragma unroll
        for (int i = 0; i < 4; ++i) {
            int o = (tid + i * 256) * 16;
            cp_async16(base + T_AH + o, s0 + o);
            cp_async16(base + T_AL + o, s1 + o);
            cp_async16(base + T_BH + o, s2 + o);
            cp_async16(base + T_BL + o, s3 + o);
        }
    };

    issue_chunk(0, 0);
    CP_COMMIT();

    for (int c = 0; c < NCHUNK_; ++c) {
        const int st = c & 1;
        if (c + 1 < NCHUNK_) {
            issue_chunk(c + 1, (c + 1) & 1);
            CP_COMMIT();
            CP_WAIT1();
        } else {
            CP_WAIT0();
        }
        __syncthreads();
        const uint32_t stb = sb + st * G_STAGE;
#pragma unroll
        for (int ks = 0; ks < 4; ++ks) {
            const int k0 = ks * 16;
            uint32_t fah[2][4], fal[2][4];
#pragma unroll
            for (int i = 0; i < 2; ++i) {
                uint32_t sw = sw128((uint32_t)((wm + 16 * i + a_row) * 128 +
                                               (k0 + a_kc8) * 2));
                ldmatrix_x4(fah[i][0], fah[i][1], fah[i][2], fah[i][3],
                            stb + T_AH + sw);
                ldmatrix_x4(fal[i][0], fal[i][1], fal[i][2], fal[i][3],
                            stb + T_AL + sw);
            }
            uint32_t fbh[4][4], fbl[4][4];
#pragma unroll
            for (int jp = 0; jp < 4; ++jp) {
                uint32_t sw = sw128((uint32_t)((wn + 16 * jp + b_row) * 128 +
                                               (k0 + b_kc8) * 2));
                ldmatrix_x4(fbh[jp][0], fbh[jp][1], fbh[jp][2], fbh[jp][3],
                            stb + T_BH + sw);
                ldmatrix_x4(fbl[jp][0], fbl[jp][1], fbl[jp][2], fbl[jp][3],
                            stb + T_BL + sw);
            }
#pragma unroll
            for (int i = 0; i < 2; ++i)
#pragma unroll
                for (int j = 0; j < 8; ++j) {
                    int jp = j >> 1, rr = (j & 1) * 2;
                    mma16816(acc[i][j], fah[i], fbh[jp][rr], fbh[jp][rr + 1]);
                    mma16816(acc[i][j], fah[i], fbl[jp][rr], fbl[jp][rr + 1]);
                    mma16816(acc[i][j], fal[i], fbh[jp][rr], fbh[jp][rr + 1]);
                }
        }
        __syncthreads();
    }

    const int g = lid >> 2, t = lid & 3;

    // Fused RoPE for Q/K (MODE 0, z<2): lane holds cols d and d+32 at j, j+4.
    if (MODE == 0 && z < 2) {
#pragma unroll
        for (int i = 0; i < 2; ++i) {
#pragma unroll
            for (int half = 0; half < 2; ++half) {
                int row = bm * 128 + wm + 16 * i + g + half * 8;
                int s = row & (S_ - 1);
#pragma unroll
                for (int j = 0; j < 4; ++j) {
#pragma unroll
                    for (int e = 0; e < 2; ++e) {
                        int dd = 8 * j + 2 * t + e;   // < 32
                        float cs = g_cosT[s * 32 + dd];
                        float sn = g_sinT[s * 32 + dd];
                        float x1 = acc[i][j][2 * half + e];
                        float x2 = acc[i][j + 4][2 * half + e];
                        acc[i][j][2 * half + e]     = x1 * cs - x2 * sn;
                        acc[i][j + 4][2 * half + e] = x2 * cs + x1 * sn;
                    }
                }
            }
        }
    }

    __nv_bfloat16* th = (z == 0) ? g_qh : g_kh;
    __nv_bfloat16* tl = (z == 0) ? g_ql : g_kl;

#pragma unroll
    for (int i = 0; i < 2; ++i) {
#pragma unroll
        for (int j = 0; j < 8; ++j) {
            int row0 = bm * 128 + wm + 16 * i + g;
            int n = bn * 128 + wn + 8 * j + 2 * t;
#pragma unroll
            for (int half = 0; half < 2; ++half) {
                int row = row0 + half * 8;
                float2 v = make_float2(acc[i][j][half * 2 + 0],
                                       acc[i][j][half * 2 + 1]);
                if (MODE == 0) {
                    int bb = row >> 11;
                    int ss = row & (S_ - 1);
                    int hh = n >> 6;
                    int dd = n & 63;
                    *(float2*)(dst + (((size_t)(bb * H_ + hh) * S_ + ss) << 6) + dd) = v;
                    if (z < 2) {
                        size_t tile = (size_t)((bb * H_ + hh) * 32 + (ss >> 6)) * 4096;
                        uint32_t sw = sw128((uint32_t)((ss & 63) * 128 + dd * 2));
                        __nv_bfloat16 h0 = __float2bfloat16(v.x);
                        __nv_bfloat16 h1 = __float2bfloat16(v.y);
                        __nv_bfloat16 l0 = __float2bfloat16(v.x - __bfloat162float(h0));
                        __nv_bfloat16 l1 = __float2bfloat16(v.y - __bfloat162float(h1));
                        *(__nv_bfloat162*)(th + tile + (sw >> 1)) = __nv_bfloat162(h0, h1);
                        *(__nv_bfloat162*)(tl + tile + (sw >> 1)) = __nv_bfloat162(l0, l1);
                    }
                } else {
                    *(float2*)(dst + (size_t)row * HID_ + n) = v;
                }
            }
        }
    }
}

// ---------------------------------------------------------------------------
__global__ __launch_bounds__(256) void brep_kernel() {
    __shared__ float red[4][64];
    int blk = blockIdx.x;
    int bh = blk >> 3;
    int nbk = blk & 7;
    int d = threadIdx.x & 63;
    int qd = threadIdx.x >> 6;
    const float* kp = g_k + ((size_t)bh * S_ + nbk * BS_ + qd * 64) * 64 + d;
    float sum = 0.0f;
#pragma unroll 8
    for (int i = 0; i < 64; ++i) sum += kp[(size_t)i * 64];
    red[qd][d] = sum;
    __syncthreads();
    if (qd == 0) {
        float t = red[0][d] + red[1][d] + red[2][d] + red[3][d];
        g_brep[(size_t)blk * 64 + d] = t * (1.0f / 256.0f);
    }
}

__global__ __launch_bounds__(128) void select_kernel() {
    __shared__ float Qsh[128 * 65];
    __shared__ float Bsh[NB_ * 64];
    const int tid = threadIdx.x;
    const size_t qbase = (size_t)blockIdx.x * 128;
    const int bh = (int)(qbase >> 11);

    for (int off = tid; off < NB_ * 64; off += 128)
        Bsh[off] = g_brep[(size_t)bh * (NB_ * 64) + off];
    const float* qp = g_q + qbase * 64;
    for (int off = tid; off < 128 * 64; off += 128)
        Qsh[(off >> 6) * 65 + (off & 63)] = qp[off];
    __syncthreads();

    int qidx = (int)qbase + tid;
    int s = qidx & (S_ - 1);
    int cur = s >> 8;
    const float* qr = Qsh + tid * 65;

    float sc[NB_];
#pragma unroll
    for (int j = 0; j < NB_; ++j) {
        if (j > cur) { sc[j] = -INFINITY; continue; }
        if (j == cur) { sc[j] = 3.402823466e38f; continue; }
        float dd = 0.0f;
#pragma unroll 8
        for (int d = 0; d < 64; ++d) dd = fmaf(qr[d], Bsh[j * 64 + d], dd);
        sc[j] = dd;
    }

    unsigned msk = 0;
    bool used[NB_];
#pragma unroll
    for (int j = 0; j < NB_; ++j) used[j] = false;
#pragma unroll
    for (int t = 0; t < TK_; ++t) {
        int bi = -1; float bv = 0.0f;
#pragma unroll
        for (int j = 0; j < NB_; ++j) {
            if (!used[j] && (bi < 0 || sc[j] > bv)) { bi = j; bv = sc[j]; }
        }
        used[bi] = true;
        msk |= 1u << bi;
    }
    g_mask[qidx] = (unsigned char)msk;
}

// ---------------------------------------------------------------------------
// Sparse flash attention on HMMA (bf16x3), cp.async double-buffered K/V.
// grid = (32, 12, 2), 128 threads; qt reversed for load balance.
// smem: Q 16KB | 2 stages x 32KB (KH|KL|VH|VL 8KB each) = 80KB.
// ---------------------------------------------------------------------------
#define AT_QH 0
#define AT_QL 8192
#define AT_KV 16384
#define A_STAGE 32768
#define ATTN_SMEM (AT_KV + 2 * A_STAGE)

__global__ __launch_bounds__(128) void attn_kernel() {
    extern __shared__ char smem[];
    const uint32_t sb = smem_u32(smem);
    const int tid = threadIdx.x;
    const int wid = tid >> 5, lid = tid & 31;
    const int qt = (int)(gridDim.x - 1 - blockIdx.x);   // heavy tiles first
    const int h = blockIdx.y, b = blockIdx.z;
    const int q0 = qt * 64;
    const int bh = b * H_ + h;
    const int wq = wid * 16;

    // Load Q tiles (once, plain copy)
    {
        const uint4* s0 = (const uint4*)(g_qh + (size_t)(bh * 32 + qt) * 4096);
        const uint4* s1 = (const uint4*)(g_ql + (size_t)(bh * 32 + qt) * 4096);
        uint4* d0 = (uint4*)(smem + AT_QH);
        uint4* d1 = (uint4*)(smem + AT_QL);
#pragma unroll
        for (int i = 0; i < 4; ++i) {
            int o = tid + i * 128;
            d0[o] = s0[o];
            d1[o] = s1[o];
        }
    }
    __syncthreads();

    const int a_row = lid & 15;
    const int a_k8 = (lid >> 4) << 3;
    const int b_row = (lid & 7) + ((lid >> 4) << 3);
    const int b_k8 = ((lid >> 3) & 1) << 3;
    uint32_t fqh[4][4], fql[4][4];
#pragma unroll
    for (int ks = 0; ks < 4; ++ks) {
        uint32_t sw = sw128((uint32_t)((wq + a_row) * 128 + (ks * 16 + a_k8) * 2));
        ldmatrix_x4(fqh[ks][0], fqh[ks][1], fqh[ks][2], fqh[ks][3], sb + AT_QH + sw);
        ldmatrix_x4(fql[ks][0], fql[ks][1], fql[ks][2], fql[ks][3], sb + AT_QL + sw);
    }

    const int g = lid >> 2;
    const int qq = (lid & 3) * 2;
    const int r0 = q0 + wq + g;
    const int r1 = r0 + 8;
    const unsigned msk0 = g_mask[(size_t)bh * S_ + r0];
    const unsigned msk1 = g_mask[(size_t)bh * S_ + r1];

    const int cur = q0 >> 8;
    const int nkt = ((cur >= 2) ? (cur + 1) : 3) * 4;

    float mrow0 = -INFINITY, mrow1 = -INFINITY, lrow0 = 0.0f, lrow1 = 0.0f;
    float acc_o[8][4];
#pragma unroll
    for (int j = 0; j < 8; ++j)
#pragma unroll
        for (int r = 0; r < 4; ++r) acc_o[j][r] = 0.0f;

    auto issue_kv = [&](int kt, int st) {
        size_t tb = (size_t)(bh * 32 + kt) * 4096;
        uint32_t base = sb + AT_KV + st * A_STAGE;
        const char* s0 = (const char*)(g_kh + tb);
        const char* s1 = (const char*)(g_kl + tb);
        const char* s2 = (const char*)(g_vth + tb);
        const char* s3 = (const char*)(g_vtl + tb);
#pragma unroll
        for (int i = 0; i < 4; ++i) {
            int o = (tid + i * 128) * 16;
            cp_async16(base + 0 + o, s0 + o);
            cp_async16(base + 8192 + o, s1 + o);
            cp_async16(base + 16384 + o, s2 + o);
            cp_async16(base + 24576 + o, s3 + o);
        }
    };

    issue_kv(0, 0);
    CP_COMMIT();

    for (int kt = 0; kt < nkt; ++kt) {
        const int k0 = kt * 64;
        const int jb = kt >> 2;
        const int st = kt & 1;
        if (kt + 1 < nkt) {
            issue_kv(kt + 1, (kt + 1) & 1);
            CP_COMMIT();
            CP_WAIT1();
        } else {
            CP_WAIT0();
        }
        __syncthreads();
        const uint32_t kb = sb + AT_KV + st * A_STAGE;

        // S = Q K^T (bf16x3)
        float s[8][4];
#pragma unroll
        for (int j = 0; j < 8; ++j)
#pragma unroll
            for (int r = 0; r < 4; ++r) s[j][r] = 0.0f;
#pragma unroll
        for (int ks = 0; ks < 4; ++ks) {
            uint32_t fkh[4][4], fkl[4][4];
#pragma unroll
            for (int jp = 0; jp < 4; ++jp) {
                uint32_t sw = sw128((uint32_t)((jp * 16 + b_row) * 128 +
                                               (ks * 16 + b_k8) * 2));
                ldmatrix_x4(fkh[jp][0], fkh[jp][1], fkh[jp][2], fkh[jp][3],
                            kb + 0 + sw);
                ldmatrix_x4(fkl[jp][0], fkl[jp][1], fkl[jp][2], fkl[jp][3],
                            kb + 8192 + sw);
            }
#pragma unroll
            for (int j = 0; j < 8; ++j) {
                int jp = j >> 1, rr = (j & 1) * 2;
                mma16816(s[j], fqh[ks], fkh[jp][rr], fkh[jp][rr + 1]);
                mma16816(s[j], fqh[ks], fkl[jp][rr], fkl[jp][rr + 1]);
                mma16816(s[j], fql[ks], fkh[jp][rr], fkh[jp][rr + 1]);
            }
        }

        // Mask + scale + online softmax
        const bool sel0 = (msk0 >> jb) & 1u;
        const bool sel1 = (msk1 >> jb) & 1u;
        float mx0 = -INFINITY, mx1 = -INFINITY;
#pragma unroll
        for (int j = 0; j < 8; ++j) {
#pragma unroll
            for (int e = 0; e < 2; ++e) {
                int kg = k0 + j * 8 + qq + e;
                bool v0 = sel0 && (jb != cur || kg <= r0);
                bool v1 = sel1 && (jb != cur || kg <= r1);
                float s0v = v0 ? s[j][e] * 0.125f : -INFINITY;
                float s1v = v1 ? s[j][2 + e] * 0.125f : -INFINITY;
                s[j][e] = s0v;
                s[j][2 + e] = s1v;
                mx0 = fmaxf(mx0, s0v);
                mx1 = fmaxf(mx1, s1v);
            }
        }
#pragma unroll
        for (int off = 1; off <= 2; off <<= 1) {
            mx0 = fmaxf(mx0, __shfl_xor_sync(0xffffffffu, mx0, off));
            mx1 = fmaxf(mx1, __shfl_xor_sync(0xffffffffu, mx1, off));
        }
        float newm0 = fmaxf(mrow0, mx0);
        float newm1 = fmaxf(mrow1, mx1);
        float fac0 = (mrow0 == -INFINITY) ? 0.0f : __expf(mrow0 - newm0);
        float fac1 = (mrow1 == -INFINITY) ? 0.0f : __expf(mrow1 - newm1);
        float rs0 = 0.0f, rs1 = 0.0f;
#pragma unroll
        for (int j = 0; j < 8; ++j) {
#pragma unroll
            for (int e = 0; e < 2; ++e) {
                float p0 = (s[j][e] == -INFINITY) ? 0.0f : __expf(s[j][e] - newm0);
                float p1 = (s[j][2 + e] == -INFINITY) ? 0.0f : __expf(s[j][2 + e] - newm1);
                s[j][e] = p0;
                s[j][2 + e] = p1;
                rs0 += p0;
                rs1 += p1;
            }
        }
#pragma unroll
        for (int off = 1; off <= 2; off <<= 1) {
            rs0 += __shfl_xor_sync(0xffffffffu, rs0, off);
            rs1 += __shfl_xor_sync(0xffffffffu, rs1, off);
        }
        lrow0 = lrow0 * fac0 + rs0;
        lrow1 = lrow1 * fac1 + rs1;
        mrow0 = newm0;
        mrow1 = newm1;
#pragma unroll
        for (int j = 0; j < 8; ++j) {
            acc_o[j][0] *= fac0;
            acc_o[j][1] *= fac0;
            acc_o[j][2] *= fac1;
            acc_o[j][3] *= fac1;
        }

        // acc_o += P V
#pragma unroll
        for (int j0 = 0; j0 < 4; ++j0) {
            const int j = 2 * j0;
            float h00 = __bfloat162float(__float2bfloat16(s[j][0]));
            float h01 = __bfloat162float(__float2bfloat16(s[j][1]));
            float h02 = __bfloat162float(__float2bfloat16(s[j][2]));
            float h03 = __bfloat162float(__float2bfloat16(s[j][3]));
            float h10 = __bfloat162float(__float2bfloat16(s[j + 1][0]));
            float h11 = __bfloat162float(__float2bfloat16(s[j + 1][1]));
            float h12 = __bfloat162float(__float2bfloat16(s[j + 1][2]));
            float h13 = __bfloat162float(__float2bfloat16(s[j + 1][3]));
            uint32_t ph[4], pl[4];
            ph[0] = bf16x2_pack(s[j][0], s[j][1]);
            ph[1] = bf16x2_pack(s[j][2], s[j][3]);
            ph[2] = bf16x2_pack(s[j + 1][0], s[j + 1][1]);
            ph[3] = bf16x2_pack(s[j + 1][2], s[j + 1][3]);
            pl[0] = bf16x2_pack(s[j][0] - h00, s[j][1] - h01);
            pl[1] = bf16x2_pack(s[j][2] - h02, s[j][3] - h03);
            pl[2] = bf16x2_pack(s[j + 1][0] - h10, s[j + 1][1] - h11);
            pl[3] = bf16x2_pack(s[j + 1][2] - h12, s[j + 1][3] - h13);

            uint32_t fvh[4][4], fvl[4][4];
#pragma unroll
            for (int jp = 0; jp < 4; ++jp) {
                uint32_t sw = sw128((uint32_t)((jp * 16 + b_row) * 128 +
                                               (j0 * 16 + b_k8) * 2));
                ldmatrix_x4(fvh[jp][0], fvh[jp][1], fvh[jp][2], fvh[jp][3],
                            kb + 16384 + sw);
                ldmatrix_x4(fvl[jp][0], fvl[jp][1], fvl[jp][2], fvl[jp][3],
                            kb + 24576 + sw);
            }
#pragma unroll
            for (int jn = 0; jn < 8; ++jn) {
                int jp = jn >> 1, rr = (jn & 1) * 2;
                mma16816(acc_o[jn], ph, fvh[jp][rr], fvh[jp][rr + 1]);
                mma16816(acc_o[jn], ph, fvl[jp][rr], fvl[jp][rr + 1]);
                mma16816(acc_o[jn], pl, fvh[jp][rr], fvh[jp][rr + 1]);
            }
        }
        __syncthreads();
    }

    float inv0 = 1.0f / lrow0;
    float inv1 = 1.0f / lrow1;
#pragma unroll
    for (int j = 0; j < 8; ++j) {
        int n = j * 8 + qq;
        float2 v0 = make_float2(acc_o[j][0] * inv0, acc_o[j][1] * inv0);
        float2 v1 = make_float2(acc_o[j][2] * inv1, acc_o[j][3] * inv1);
        *(float2*)(g_attn + ((size_t)(b * S_ + r0) * H_ + h) * 64 + n) = v0;
        *(float2*)(g_attn + ((size_t)(b * S_ + r1) * H_ + h) * 64 + n) = v1;
    }
}

// ---------------------------------------------------------------------------
extern "C" void kernel_launch(void* const* d_in, const int* in_sizes, int n_in,
                              void* d_out, int out_size) {
    const float* hidden = (const float*)d_in[0];
    const float* Wq = (const float*)d_in[1];
    const float* Wk = (const float*)d_in[2];
    const float* Wv = (const float*)d_in[3];
    const float* Wo = (const float*)d_in[4];

    static bool attr_done = false;
    if (!attr_done) {
        cudaFuncSetAttribute(mma_gemm_kernel<0>,
                             cudaFuncAttributeMaxDynamicSharedMemorySize,
                             GEMM_SMEM_BYTES);
        cudaFuncSetAttribute(mma_gemm_kernel<1>,
                             cudaFuncAttributeMaxDynamicSharedMemorySize,
                             GEMM_SMEM_BYTES);
        cudaFuncSetAttribute(attn_kernel,
                             cudaFuncAttributeMaxDynamicSharedMemorySize,
                             ATTN_SMEM);
        attr_done = true;
    }

    init_tab_kernel<<<(S_ * 32 + 255) / 256, 256>>>();

    conv_all_kernel<<<(NA_CONV + 4 * NW_CONV + 255) / 256, 256>>>(
        hidden, Wq, Wk, Wv, Wo);

    // QKV projections (HMMA) with fused RoPE + bf16 attention-tile epilogue
    mma_gemm_kernel<0><<<dim3(HID_ / 128, M_ / 128, 3), 256, GEMM_SMEM_BYTES>>>(nullptr);

    brep_kernel<<<B_ * H_ * NB_, 256>>>();
    select_kernel<<<B_ * H_ * S_ / 128, 128>>>();
    conv_v_kernel<<<(B_ * H_ * S_ * 32 + 255) / 256, 256>>>();

    attn_kernel<<<dim3(S_ / 64, H_, B_), 128, ATTN_SMEM>>>();

    conv_attn_kernel<<<(NA_CONV + 255) / 256, 256>>>();
    mma_gemm_kernel<1><<<dim3(HID_ / 128, M_ / 128), 256, GEMM_SMEM_BYTES>>>((float*)d_out);
}

// round 9
// speedup vs baseline: 4.0591x; 1.1709x over previous
#include <cuda_runtime.h>
#include <cuda_bf16.h>
#include <math.h>
#include <float.h>
#include <stdint.h>

// Problem constants
#define B_   2
#define S_   2048
#define HID_ 768
#define H_   12
#define D_   64
#define BS_  256
#define NB_  8
#define TK_  3
#define M_   (B_ * S_)          // 4096 token rows
#define NCHUNK_ 12              // 768 / 64 K-chunks

// Scratch (device globals; no runtime allocation allowed)
__device__ float g_q[B_ * H_ * S_ * D_];
__device__ float g_k[B_ * H_ * S_ * D_];
__device__ float g_brep[B_ * H_ * NB_ * D_];
__device__ unsigned char g_mask[B_ * H_ * S_];
__device__ float g_sinT[S_ * 32];
__device__ float g_cosT[S_ * 32];

// bf16 split operands, pre-swizzled tiles (SW128, K-major rows of 128B)
__device__ __nv_bfloat16 g_ah[M_ * HID_];       // GEMM A hi (hidden, later attn out)
__device__ __nv_bfloat16 g_al[M_ * HID_];       // GEMM A lo
__device__ __nv_bfloat16 g_wh[4][HID_ * HID_];  // Wq,Wk,Wv,Wo hi
__device__ __nv_bfloat16 g_wl[4][HID_ * HID_];  // lo

// Attention operands: 64x64 tiles, tile idx = bh*32 + t64 (4096 elems/tile)
__device__ __nv_bfloat16 g_qh[B_ * H_ * S_ * D_];
__device__ __nv_bfloat16 g_ql[B_ * H_ * S_ * D_];
__device__ __nv_bfloat16 g_kh[B_ * H_ * S_ * D_];
__device__ __nv_bfloat16 g_kl[B_ * H_ * S_ * D_];
__device__ __nv_bfloat16 g_vth[B_ * H_ * S_ * D_];  // V transposed [d][key]
__device__ __nv_bfloat16 g_vtl[B_ * H_ * S_ * D_];

__device__ __forceinline__ uint32_t smem_u32(const void* p) {
    uint32_t a;
    asm("{ .reg .u64 t; cvta.to.shared.u64 t, %1; cvt.u32.u64 %0, t; }"
        : "=r"(a) : "l"(p));
    return a;
}
__device__ __forceinline__ uint32_t sw128(uint32_t off) {
    return off ^ ((off >> 3) & 0x70);
}
__device__ __forceinline__ void cp_async16(uint32_t saddr, const void* gptr) {
    asm volatile("cp.async.cg.shared.global [%0], [%1], 16;"
                 :: "r"(saddr), "l"(gptr));
}
#define CP_COMMIT() asm volatile("cp.async.commit_group;" ::: "memory")
#define CP_WAIT1()  asm volatile("cp.async.wait_group 1;" ::: "memory")
#define CP_WAIT0()  asm volatile("cp.async.wait_group 0;" ::: "memory")

// ---------------------------------------------------------------------------
// HMMA helpers
// ---------------------------------------------------------------------------
__device__ __forceinline__ void ldmatrix_x4(uint32_t& r0, uint32_t& r1,
                                            uint32_t& r2, uint32_t& r3,
                                            uint32_t addr) {
    asm volatile("ldmatrix.sync.aligned.m8n8.x4.shared.b16 {%0,%1,%2,%3}, [%4];"
                 : "=r"(r0), "=r"(r1), "=r"(r2), "=r"(r3) : "r"(addr));
}
__device__ __forceinline__ void mma16816(float* c, const uint32_t* a,
                                         uint32_t b0, uint32_t b1) {
    asm volatile(
        "mma.sync.aligned.m16n8k16.row.col.f32.bf16.bf16.f32 "
        "{%0,%1,%2,%3}, {%4,%5,%6,%7}, {%8,%9}, {%0,%1,%2,%3};"
        : "+f"(c[0]), "+f"(c[1]), "+f"(c[2]), "+f"(c[3])
        : "r"(a[0]), "r"(a[1]), "r"(a[2]), "r"(a[3]), "r"(b0), "r"(b1));
}
__device__ __forceinline__ uint32_t bf16x2_pack(float lo, float hi) {
    uint32_t r;
    asm("cvt.rn.bf16x2.f32 %0, %1, %2;" : "=r"(r) : "f"(hi), "f"(lo));
    return r;
}

// ---------------------------------------------------------------------------
// sin/cos tables (ang = s * invf[i], invf from double exp — matches ref path)
// ---------------------------------------------------------------------------
__global__ __launch_bounds__(256) void init_tab_kernel() {
    int idx = blockIdx.x * 256 + threadIdx.x;
    if (idx >= S_ * 32) return;
    int i = idx & 31;
    int s = idx >> 5;
    float inv = (float)exp(-9.210340371976184 * (double)i / 32.0);
    float ang = (float)s * inv;
    g_sinT[idx] = sinf(ang);
    g_cosT[idx] = cosf(ang);
}

// ---------------------------------------------------------------------------
// Merged input conversion: hidden + 4 weights -> bf16 hi/lo swizzled tiles.
// ---------------------------------------------------------------------------
#define NA_CONV (M_ * 384)
#define NW_CONV (HID_ * 384)
__global__ __launch_bounds__(256) void conv_all_kernel(
    const float* __restrict__ hidden, const float* __restrict__ W0,
    const float* __restrict__ W1, const float* __restrict__ W2,
    const float* __restrict__ W3) {
    int idx = blockIdx.x * 256 + threadIdx.x;
    if (idx >= NA_CONV + 4 * NW_CONV) return;
    const float* src;
    __nv_bfloat16 *dh, *dl;
    int li;
    if (idx < NA_CONV) {
        src = hidden; dh = g_ah; dl = g_al; li = idx;
    } else {
        int w = (idx - NA_CONV) / NW_CONV;
        li = (idx - NA_CONV) - w * NW_CONV;
        src = (w == 0) ? W0 : (w == 1) ? W1 : (w == 2) ? W2 : W3;
        dh = g_wh[w]; dl = g_wl[w];
    }
    int rg  = li / 384;
    int col = (li - rg * 384) * 2;
    int mtile = rg >> 7;
    int r = rg & 127;
    int chunk = col >> 6;
    int cc = col & 63;
    uint32_t sw = sw128((uint32_t)(r * 128 + cc * 2));
    size_t dst_half = (size_t)(mtile * NCHUNK_ + chunk) * 8192 + (sw >> 1);
    float2 v = *(const float2*)(src + (size_t)rg * HID_ + col);
    __nv_bfloat16 h0 = __float2bfloat16(v.x);
    __nv_bfloat16 h1 = __float2bfloat16(v.y);
    __nv_bfloat16 l0 = __float2bfloat16(v.x - __bfloat162float(h0));
    __nv_bfloat16 l1 = __float2bfloat16(v.y - __bfloat162float(h1));
    *(__nv_bfloat162*)(dh + dst_half) = __nv_bfloat162(h0, h1);
    *(__nv_bfloat162*)(dl + dst_half) = __nv_bfloat162(l0, l1);
}

// ---------------------------------------------------------------------------
// HMMA GEMM, cp.async double-buffered.
// MODE 0: QKV. z<2: fused RoPE; writes fp32 (b,h,s,d) AND bf16 attn tiles.
//         z==2 (V): writes ONLY transposed bf16 hi/lo attention tiles.
// MODE 1: O-projection into out (A = g_ah/g_al written by attention).
// ---------------------------------------------------------------------------
#define T_AH 0
#define T_AL 16384
#define T_BH 32768
#define T_BL 49152
#define G_STAGE 65536
#define GEMM_SMEM_BYTES (2 * G_STAGE)

template <int MODE>
__global__ __launch_bounds__(256) void mma_gemm_kernel(float* __restrict__ out) {
    extern __shared__ char smem[];
    const uint32_t sb = smem_u32(smem);
    const int tid = threadIdx.x;
    const int wid = tid >> 5, lid = tid & 31;
    const int bn = blockIdx.x;
    const int bm = blockIdx.y;
    const int wm = (wid & 3) * 32;
    const int wn = (wid >> 2) * 64;
    const int z = (MODE == 0) ? blockIdx.z : 3;

    const __nv_bfloat16 *Ah, *Al, *Bh, *Bl;
    Ah = g_ah; Al = g_al;
    Bh = g_wh[z]; Bl = g_wl[z];

    float acc[2][8][4];
#pragma unroll
    for (int i = 0; i < 2; ++i)
#pragma unroll
        for (int j = 0; j < 8; ++j)
#pragma unroll
            for (int r = 0; r < 4; ++r) acc[i][j][r] = 0.0f;

    const size_t a_base = (size_t)bm * NCHUNK_ * 8192;
    const size_t b_base = (size_t)bn * NCHUNK_ * 8192;

    const int a_row = (lid & 15);
    const int a_kc8 = (lid >> 4) << 3;
    const int b_row = (lid & 7) + ((lid >> 4) << 3);
    const int b_kc8 = ((lid >> 3) & 1) << 3;

    auto issue_chunk = [&](int c, int st) {
        uint32_t base = sb + st * G_STAGE;
        const char* s0 = (const char*)(Ah + a_base + (size_t)c * 8192);
        const char* s1 = (const char*)(Al + a_base + (size_t)c * 8192);
        const char* s2 = (const char*)(Bh + b_base + (size_t)c * 8192);
        const char* s3 = (const char*)(Bl + b_base + (size_t)c * 8192);
#pragma unroll
        for (int i = 0; i < 4; ++i) {
            int o = (tid + i * 256) * 16;
            cp_async16(base + T_AH + o, s0 + o);
            cp_async16(base + T_AL + o, s1 + o);
            cp_async16(base + T_BH + o, s2 + o);
            cp_async16(base + T_BL + o, s3 + o);
        }
    };

    issue_chunk(0, 0);
    CP_COMMIT();

    for (int c = 0; c < NCHUNK_; ++c) {
        const int st = c & 1;
        if (c + 1 < NCHUNK_) {
            issue_chunk(c + 1, (c + 1) & 1);
            CP_COMMIT();
            CP_WAIT1();
        } else {
            CP_WAIT0();
        }
        __syncthreads();
        const uint32_t stb = sb + st * G_STAGE;
#pragma unroll
        for (int ks = 0; ks < 4; ++ks) {
            const int k0 = ks * 16;
            uint32_t fah[2][4], fal[2][4];
#pragma unroll
            for (int i = 0; i < 2; ++i) {
                uint32_t sw = sw128((uint32_t)((wm + 16 * i + a_row) * 128 +
                                               (k0 + a_kc8) * 2));
                ldmatrix_x4(fah[i][0], fah[i][1], fah[i][2], fah[i][3],
                            stb + T_AH + sw);
                ldmatrix_x4(fal[i][0], fal[i][1], fal[i][2], fal[i][3],
                            stb + T_AL + sw);
            }
            uint32_t fbh[4][4], fbl[4][4];
#pragma unroll
            for (int jp = 0; jp < 4; ++jp) {
                uint32_t sw = sw128((uint32_t)((wn + 16 * jp + b_row) * 128 +
                                               (k0 + b_kc8) * 2));
                ldmatrix_x4(fbh[jp][0], fbh[jp][1], fbh[jp][2], fbh[jp][3],
                            stb + T_BH + sw);
                ldmatrix_x4(fbl[jp][0], fbl[jp][1], fbl[jp][2], fbl[jp][3],
                            stb + T_BL + sw);
            }
#pragma unroll
            for (int i = 0; i < 2; ++i)
#pragma unroll
                for (int j = 0; j < 8; ++j) {
                    int jp = j >> 1, rr = (j & 1) * 2;
                    mma16816(acc[i][j], fah[i], fbh[jp][rr], fbh[jp][rr + 1]);
                    mma16816(acc[i][j], fah[i], fbl[jp][rr], fbl[jp][rr + 1]);
                    mma16816(acc[i][j], fal[i], fbh[jp][rr], fbh[jp][rr + 1]);
                }
        }
        __syncthreads();
    }

    const int g = lid >> 2, t = lid & 3;

    // Fused RoPE for Q/K (MODE 0, z<2): lane holds cols d and d+32 at j, j+4.
    if (MODE == 0 && z < 2) {
#pragma unroll
        for (int i = 0; i < 2; ++i) {
#pragma unroll
            for (int half = 0; half < 2; ++half) {
                int row = bm * 128 + wm + 16 * i + g + half * 8;
                int s = row & (S_ - 1);
#pragma unroll
                for (int j = 0; j < 4; ++j) {
#pragma unroll
                    for (int e = 0; e < 2; ++e) {
                        int dd = 8 * j + 2 * t + e;   // < 32
                        float cs = g_cosT[s * 32 + dd];
                        float sn = g_sinT[s * 32 + dd];
                        float x1 = acc[i][j][2 * half + e];
                        float x2 = acc[i][j + 4][2 * half + e];
                        acc[i][j][2 * half + e]     = x1 * cs - x2 * sn;
                        acc[i][j + 4][2 * half + e] = x2 * cs + x1 * sn;
                    }
                }
            }
        }
    }

#pragma unroll
    for (int i = 0; i < 2; ++i) {
#pragma unroll
        for (int j = 0; j < 8; ++j) {
            int row0 = bm * 128 + wm + 16 * i + g;
            int n = bn * 128 + wn + 8 * j + 2 * t;
#pragma unroll
            for (int half = 0; half < 2; ++half) {
                int row = row0 + half * 8;
                float2 v = make_float2(acc[i][j][half * 2 + 0],
                                       acc[i][j][half * 2 + 1]);
                if (MODE == 0) {
                    int bb = row >> 11;
                    int ss = row & (S_ - 1);
                    int hh = n >> 6;
                    int dd = n & 63;
                    __nv_bfloat16 h0 = __float2bfloat16(v.x);
                    __nv_bfloat16 h1 = __float2bfloat16(v.y);
                    __nv_bfloat16 l0 = __float2bfloat16(v.x - __bfloat162float(h0));
                    __nv_bfloat16 l1 = __float2bfloat16(v.y - __bfloat162float(h1));
                    size_t tile = (size_t)((bb * H_ + hh) * 32 + (ss >> 6)) * 4096;
                    if (z < 2) {
                        float* dst = (z == 0) ? g_q : g_k;
                        *(float2*)(dst + (((size_t)(bb * H_ + hh) * S_ + ss) << 6) + dd) = v;
                        __nv_bfloat16* th = (z == 0) ? g_qh : g_kh;
                        __nv_bfloat16* tl = (z == 0) ? g_ql : g_kl;
                        uint32_t sw = sw128((uint32_t)((ss & 63) * 128 + dd * 2));
                        *(__nv_bfloat162*)(th + tile + (sw >> 1)) = __nv_bfloat162(h0, h1);
                        *(__nv_bfloat162*)(tl + tile + (sw >> 1)) = __nv_bfloat162(l0, l1);
                    } else {
                        // V: transposed [d][key] bf16 tiles only
                        int rr2 = ss & 63;
                        uint32_t sw0 = sw128((uint32_t)(dd * 128 + rr2 * 2));
                        uint32_t sw1 = sw128((uint32_t)((dd + 1) * 128 + rr2 * 2));
                        g_vth[tile + (sw0 >> 1)] = h0;
                        g_vtl[tile + (sw0 >> 1)] = l0;
                        g_vth[tile + (sw1 >> 1)] = h1;
                        g_vtl[tile + (sw1 >> 1)] = l1;
                    }
                } else {
                    *(float2*)(out + (size_t)row * HID_ + n) = v;
                }
            }
        }
    }
}

// ---------------------------------------------------------------------------
// Block representatives: mean of roped K over 256-token blocks.  512 threads.
// ---------------------------------------------------------------------------
__global__ __launch_bounds__(512) void brep_kernel() {
    __shared__ float red[8][64];
    int blk = blockIdx.x;          // bh*8 + nb
    int bh = blk >> 3;
    int nbk = blk & 7;
    int d = threadIdx.x & 63;
    int qd = threadIdx.x >> 6;     // 0..7
    const float* kp = g_k + ((size_t)bh * S_ + nbk * BS_ + qd * 32) * 64 + d;
    float sum = 0.0f;
#pragma unroll 8
    for (int i = 0; i < 32; ++i) sum += kp[(size_t)i * 64];
    red[qd][d] = sum;
    __syncthreads();
    if (qd == 0) {
        float t = 0.0f;
#pragma unroll
        for (int i = 0; i < 8; ++i) t += red[i][d];
        g_brep[(size_t)blk * 64 + d] = t * (1.0f / 256.0f);
    }
}

__global__ __launch_bounds__(128) void select_kernel() {
    __shared__ float Qsh[128 * 65];
    __shared__ float Bsh[NB_ * 64];
    const int tid = threadIdx.x;
    const size_t qbase = (size_t)blockIdx.x * 128;
    const int bh = (int)(qbase >> 11);

    for (int off = tid; off < NB_ * 64; off += 128)
        Bsh[off] = g_brep[(size_t)bh * (NB_ * 64) + off];
    const float* qp = g_q + qbase * 64;
    for (int off = tid; off < 128 * 64; off += 128)
        Qsh[(off >> 6) * 65 + (off & 63)] = qp[off];
    __syncthreads();

    int qidx = (int)qbase + tid;
    int s = qidx & (S_ - 1);
    int cur = s >> 8;
    const float* qr = Qsh + tid * 65;

    float sc[NB_];
#pragma unroll
    for (int j = 0; j < NB_; ++j) {
        if (j > cur) { sc[j] = -INFINITY; continue; }
        if (j == cur) { sc[j] = 3.402823466e38f; continue; }
        float dd = 0.0f;
#pragma unroll 8
        for (int d = 0; d < 64; ++d) dd = fmaf(qr[d], Bsh[j * 64 + d], dd);
        sc[j] = dd;
    }

    unsigned msk = 0;
    bool used[NB_];
#pragma unroll
    for (int j = 0; j < NB_; ++j) used[j] = false;
#pragma unroll
    for (int t = 0; t < TK_; ++t) {
        int bi = -1; float bv = 0.0f;
#pragma unroll
        for (int j = 0; j < NB_; ++j) {
            if (!used[j] && (bi < 0 || sc[j] > bv)) { bi = j; bv = sc[j]; }
        }
        used[bi] = true;
        msk |= 1u << bi;
    }
    g_mask[qidx] = (unsigned char)msk;
}

// ---------------------------------------------------------------------------
// Sparse flash attention on HMMA (bf16x3), cp.async double-buffered K/V.
// grid = (32, 12, 2), 128 threads; qt reversed for load balance.
// smem 64KB: Q (16KB) overlays KV stage 0; 2 stages x 32KB.
// Epilogue writes bf16 hi/lo A-tiles for the O-projection directly.
// ---------------------------------------------------------------------------
#define A_STAGE 32768
#define ATTN_SMEM (2 * A_STAGE)

__global__ __launch_bounds__(128) void attn_kernel() {
    extern __shared__ char smem[];
    const uint32_t sb = smem_u32(smem);
    const int tid = threadIdx.x;
    const int wid = tid >> 5, lid = tid & 31;
    const int qt = (int)(gridDim.x - 1 - blockIdx.x);   // heavy tiles first
    const int h = blockIdx.y, b = blockIdx.z;
    const int q0 = qt * 64;
    const int bh = b * H_ + h;
    const int wq = wid * 16;

    // Load Q tiles into stage-0 region (consumed into fragments before reuse)
    {
        const uint4* s0 = (const uint4*)(g_qh + (size_t)(bh * 32 + qt) * 4096);
        const uint4* s1 = (const uint4*)(g_ql + (size_t)(bh * 32 + qt) * 4096);
        uint4* d0 = (uint4*)(smem);
        uint4* d1 = (uint4*)(smem + 8192);
#pragma unroll
        for (int i = 0; i < 4; ++i) {
            int o = tid + i * 128;
            d0[o] = s0[o];
            d1[o] = s1[o];
        }
    }
    __syncthreads();

    const int a_row = lid & 15;
    const int a_k8 = (lid >> 4) << 3;
    const int b_row = (lid & 7) + ((lid >> 4) << 3);
    const int b_k8 = ((lid >> 3) & 1) << 3;
    uint32_t fqh[4][4], fql[4][4];
#pragma unroll
    for (int ks = 0; ks < 4; ++ks) {
        uint32_t sw = sw128((uint32_t)((wq + a_row) * 128 + (ks * 16 + a_k8) * 2));
        ldmatrix_x4(fqh[ks][0], fqh[ks][1], fqh[ks][2], fqh[ks][3], sb + sw);
        ldmatrix_x4(fql[ks][0], fql[ks][1], fql[ks][2], fql[ks][3], sb + 8192 + sw);
    }
    __syncthreads();   // all warps done reading Q before stage 0 is overwritten

    const int g = lid >> 2;
    const int qq = (lid & 3) * 2;
    const int r0 = q0 + wq + g;
    const int r1 = r0 + 8;
    const unsigned msk0 = g_mask[(size_t)bh * S_ + r0];
    const unsigned msk1 = g_mask[(size_t)bh * S_ + r1];

    const int cur = q0 >> 8;
    const int nkt = ((cur >= 2) ? (cur + 1) : 3) * 4;

    float mrow0 = -INFINITY, mrow1 = -INFINITY, lrow0 = 0.0f, lrow1 = 0.0f;
    float acc_o[8][4];
#pragma unroll
    for (int j = 0; j < 8; ++j)
#pragma unroll
        for (int r = 0; r < 4; ++r) acc_o[j][r] = 0.0f;

    auto issue_kv = [&](int kt, int st) {
        size_t tb = (size_t)(bh * 32 + kt) * 4096;
        uint32_t base = sb + st * A_STAGE;
        const char* s0 = (const char*)(g_kh + tb);
        const char* s1 = (const char*)(g_kl + tb);
        const char* s2 = (const char*)(g_vth + tb);
        const char* s3 = (const char*)(g_vtl + tb);
#pragma unroll
        for (int i = 0; i < 4; ++i) {
            int o = (tid + i * 128) * 16;
            cp_async16(base + 0 + o, s0 + o);
            cp_async16(base + 8192 + o, s1 + o);
            cp_async16(base + 16384 + o, s2 + o);
            cp_async16(base + 24576 + o, s3 + o);
        }
    };

    issue_kv(0, 0);
    CP_COMMIT();

    for (int kt = 0; kt < nkt; ++kt) {
        const int k0 = kt * 64;
        const int jb = kt >> 2;
        const int st = kt & 1;
        if (kt + 1 < nkt) {
            issue_kv(kt + 1, (kt + 1) & 1);
            CP_COMMIT();
            CP_WAIT1();
        } else {
            CP_WAIT0();
        }
        __syncthreads();
        const uint32_t kb = sb + st * A_STAGE;

        // S = Q K^T (bf16x3)
        float s[8][4];
#pragma unroll
        for (int j = 0; j < 8; ++j)
#pragma unroll
            for (int r = 0; r < 4; ++r) s[j][r] = 0.0f;
#pragma unroll
        for (int ks = 0; ks < 4; ++ks) {
            uint32_t fkh[4][4], fkl[4][4];
#pragma unroll
            for (int jp = 0; jp < 4; ++jp) {
                uint32_t sw = sw128((uint32_t)((jp * 16 + b_row) * 128 +
                                               (ks * 16 + b_k8) * 2));
                ldmatrix_x4(fkh[jp][0], fkh[jp][1], fkh[jp][2], fkh[jp][3],
                            kb + 0 + sw);
                ldmatrix_x4(fkl[jp][0], fkl[jp][1], fkl[jp][2], fkl[jp][3],
                            kb + 8192 + sw);
            }
#pragma unroll
            for (int j = 0; j < 8; ++j) {
                int jp = j >> 1, rr = (j & 1) * 2;
                mma16816(s[j], fqh[ks], fkh[jp][rr], fkh[jp][rr + 1]);
                mma16816(s[j], fqh[ks], fkl[jp][rr], fkl[jp][rr + 1]);
                mma16816(s[j], fql[ks], fkh[jp][rr], fkh[jp][rr + 1]);
            }
        }

        // Mask + scale + online softmax
        const bool sel0 = (msk0 >> jb) & 1u;
        const bool sel1 = (msk1 >> jb) & 1u;
        float mx0 = -INFINITY, mx1 = -INFINITY;
#pragma unroll
        for (int j = 0; j < 8; ++j) {
#pragma unroll
            for (int e = 0; e < 2; ++e) {
                int kg = k0 + j * 8 + qq + e;
                bool v0 = sel0 && (jb != cur || kg <= r0);
                bool v1 = sel1 && (jb != cur || kg <= r1);
                float s0v = v0 ? s[j][e] * 0.125f : -INFINITY;
                float s1v = v1 ? s[j][2 + e] * 0.125f : -INFINITY;
                s[j][e] = s0v;
                s[j][2 + e] = s1v;
                mx0 = fmaxf(mx0, s0v);
                mx1 = fmaxf(mx1, s1v);
            }
        }
#pragma unroll
        for (int off = 1; off <= 2; off <<= 1) {
            mx0 = fmaxf(mx0, __shfl_xor_sync(0xffffffffu, mx0, off));
            mx1 = fmaxf(mx1, __shfl_xor_sync(0xffffffffu, mx1, off));
        }
        float newm0 = fmaxf(mrow0, mx0);
        float newm1 = fmaxf(mrow1, mx1);
        float fac0 = (mrow0 == -INFINITY) ? 0.0f : __expf(mrow0 - newm0);
        float fac1 = (mrow1 == -INFINITY) ? 0.0f : __expf(mrow1 - newm1);
        float rs0 = 0.0f, rs1 = 0.0f;
#pragma unroll
        for (int j = 0; j < 8; ++j) {
#pragma unroll
            for (int e = 0; e < 2; ++e) {
                float p0 = (s[j][e] == -INFINITY) ? 0.0f : __expf(s[j][e] - newm0);
                float p1 = (s[j][2 + e] == -INFINITY) ? 0.0f : __expf(s[j][2 + e] - newm1);
                s[j][e] = p0;
                s[j][2 + e] = p1;
                rs0 += p0;
                rs1 += p1;
            }
        }
#pragma unroll
        for (int off = 1; off <= 2; off <<= 1) {
            rs0 += __shfl_xor_sync(0xffffffffu, rs0, off);
            rs1 += __shfl_xor_sync(0xffffffffu, rs1, off);
        }
        lrow0 = lrow0 * fac0 + rs0;
        lrow1 = lrow1 * fac1 + rs1;
        mrow0 = newm0;
        mrow1 = newm1;
#pragma unroll
        for (int j = 0; j < 8; ++j) {
            acc_o[j][0] *= fac0;
            acc_o[j][1] *= fac0;
            acc_o[j][2] *= fac1;
            acc_o[j][3] *= fac1;
        }

        // acc_o += P V
#pragma unroll
        for (int j0 = 0; j0 < 4; ++j0) {
            const int j = 2 * j0;
            float h00 = __bfloat162float(__float2bfloat16(s[j][0]));
            float h01 = __bfloat162float(__float2bfloat16(s[j][1]));
            float h02 = __bfloat162float(__float2bfloat16(s[j][2]));
            float h03 = __bfloat162float(__float2bfloat16(s[j][3]));
            float h10 = __bfloat162float(__float2bfloat16(s[j + 1][0]));
            float h11 = __bfloat162float(__float2bfloat16(s[j + 1][1]));
            float h12 = __bfloat162float(__float2bfloat16(s[j + 1][2]));
            float h13 = __bfloat162float(__float2bfloat16(s[j + 1][3]));
            uint32_t ph[4], pl[4];
            ph[0] = bf16x2_pack(s[j][0], s[j][1]);
            ph[1] = bf16x2_pack(s[j][2], s[j][3]);
            ph[2] = bf16x2_pack(s[j + 1][0], s[j + 1][1]);
            ph[3] = bf16x2_pack(s[j + 1][2], s[j + 1][3]);
            pl[0] = bf16x2_pack(s[j][0] - h00, s[j][1] - h01);
            pl[1] = bf16x2_pack(s[j][2] - h02, s[j][3] - h03);
            pl[2] = bf16x2_pack(s[j + 1][0] - h10, s[j + 1][1] - h11);
            pl[3] = bf16x2_pack(s[j + 1][2] - h12, s[j + 1][3] - h13);

            uint32_t fvh[4][4], fvl[4][4];
#pragma unroll
            for (int jp = 0; jp < 4; ++jp) {
                uint32_t sw = sw128((uint32_t)((jp * 16 + b_row) * 128 +
                                               (j0 * 16 + b_k8) * 2));
                ldmatrix_x4(fvh[jp][0], fvh[jp][1], fvh[jp][2], fvh[jp][3],
                            kb + 16384 + sw);
                ldmatrix_x4(fvl[jp][0], fvl[jp][1], fvl[jp][2], fvl[jp][3],
                            kb + 24576 + sw);
            }
#pragma unroll
            for (int jn = 0; jn < 8; ++jn) {
                int jp = jn >> 1, rr = (jn & 1) * 2;
                mma16816(acc_o[jn], ph, fvh[jp][rr], fvh[jp][rr + 1]);
                mma16816(acc_o[jn], ph, fvl[jp][rr], fvl[jp][rr + 1]);
                mma16816(acc_o[jn], pl, fvh[jp][rr], fvh[jp][rr + 1]);
            }
        }
        __syncthreads();
    }

    // Epilogue: normalize, split to bf16 hi/lo, write O-proj A-tiles directly.
    float inv0 = 1.0f / lrow0;
    float inv1 = 1.0f / lrow1;
#pragma unroll
    for (int j = 0; j < 8; ++j) {
        int n = j * 8 + qq;              // 0..63, even
#pragma unroll
        for (int half = 0; half < 2; ++half) {
            int rg = b * S_ + (half ? r1 : r0);     // token row
            float inv = half ? inv1 : inv0;
            float vx = acc_o[j][half * 2 + 0] * inv;
            float vy = acc_o[j][half * 2 + 1] * inv;
            __nv_bfloat16 h0 = __float2bfloat16(vx);
            __nv_bfloat16 h1 = __float2bfloat16(vy);
            __nv_bfloat16 l0 = __float2bfloat16(vx - __bfloat162float(h0));
            __nv_bfloat16 l1 = __float2bfloat16(vy - __bfloat162float(h1));
            int mtile = rg >> 7;
            int r = rg & 127;
            uint32_t sw = sw128((uint32_t)(r * 128 + n * 2));
            size_t dst_half = (size_t)(mtile * NCHUNK_ + h) * 8192 + (sw >> 1);
            *(__nv_bfloat162*)(g_ah + dst_half) = __nv_bfloat162(h0, h1);
            *(__nv_bfloat162*)(g_al + dst_half) = __nv_bfloat162(l0, l1);
        }
    }
}

// ---------------------------------------------------------------------------
extern "C" void kernel_launch(void* const* d_in, const int* in_sizes, int n_in,
                              void* d_out, int out_size) {
    const float* hidden = (const float*)d_in[0];
    const float* Wq = (const float*)d_in[1];
    const float* Wk = (const float*)d_in[2];
    const float* Wv = (const float*)d_in[3];
    const float* Wo = (const float*)d_in[4];

    static bool attr_done = false;
    if (!attr_done) {
        cudaFuncSetAttribute(mma_gemm_kernel<0>,
                             cudaFuncAttributeMaxDynamicSharedMemorySize,
                             GEMM_SMEM_BYTES);
        cudaFuncSetAttribute(mma_gemm_kernel<1>,
                             cudaFuncAttributeMaxDynamicSharedMemorySize,
                             GEMM_SMEM_BYTES);
        cudaFuncSetAttribute(attn_kernel,
                             cudaFuncAttributeMaxDynamicSharedMemorySize,
                             ATTN_SMEM);
        attr_done = true;
    }

    init_tab_kernel<<<(S_ * 32 + 255) / 256, 256>>>();

    conv_all_kernel<<<(NA_CONV + 4 * NW_CONV + 255) / 256, 256>>>(
        hidden, Wq, Wk, Wv, Wo);

    // QKV projections (HMMA): fused RoPE, bf16 attn tiles, V transposed bf16
    mma_gemm_kernel<0><<<dim3(HID_ / 128, M_ / 128, 3), 256, GEMM_SMEM_BYTES>>>(nullptr);

    brep_kernel<<<B_ * H_ * NB_, 512>>>();
    select_kernel<<<B_ * H_ * S_ / 128, 128>>>();

    attn_kernel<<<dim3(S_ / 64, H_, B_), 128, ATTN_SMEM>>>();

    // O projection straight from attention's bf16 tiles into d_out
    mma_gemm_kernel<1><<<dim3(HID_ / 128, M_ / 128), 256, GEMM_SMEM_BYTES>>>((float*)d_out);
}